// round 5
// baseline (speedup 1.0000x reference)
#include <cuda_runtime.h>
#include <math.h>
#include <stdint.h>

// ----------------------------------------------------------------------------
// ODELSTMCell: B=16384, I=128, H=256
//   ODE: 8 fixed RK45 (dopri5) steps of f(h)=tanh(h@W1^T+b1)@W2^T+b2,
//   then two weight-shared LSTM cells.
// R5 strategy: persistent-tile CTA (MT=16 rows, 1024 CTAs), state in SMEM
// transposed [256][ST]. GEMM register tiling TJ=2 x TM=8: thread (mh=t>>7,
// jj=t&127) computes columns {jj, jj+128} for rows [mh*8, mh*8+8). Weights
// pre-packed as float2 column pairs so the inner loop per k is:
//   1 LDG.64 (weights) + 2 broadcast LDS.128 (activations) + 8 FFMA2.
// This halves the L1/shared wavefront load vs R4 (which was smem-read bound
// at L1=87.7%) while keeping the FMA count identical.
// ----------------------------------------------------------------------------

#define B_TOTAL 16384
#define HDIM    256
#define IDIM    128
#define MT      16     // batch rows per CTA  (16384 / 16 = 1024 CTAs)
#define ST      20     // smem row stride in floats
#define NSTEPS  8

// --- packed transposed weight scratch ---
// g_W1p[k*128 + jj] = ( W1[jj][k], W1[jj+128][k] )          [256][128] float2
// g_W2p same layout.
// g_Wihp[k*512 + q*128 + jj] = ( Wih[q*256+jj][k], Wih[q*256+jj+128][k] )  [128][512]
// g_Whhp[k*512 + q*128 + jj] = ( Whh[q*256+jj][k], Whh[q*256+jj+128][k] )  [256][512]
__device__ float2 g_W1p [HDIM * 128];
__device__ float2 g_W2p [HDIM * 128];
__device__ float2 g_Wihp[IDIM * 512];
__device__ float2 g_Whhp[HDIM * 512];

__global__ void prep_kernel(const float* __restrict__ W1, const float* __restrict__ W2,
                            const float* __restrict__ Wih, const float* __restrict__ Whh) {
    int i0 = blockIdx.x * blockDim.x + threadIdx.x;
    int gs = gridDim.x * blockDim.x;
    for (int p = i0; p < HDIM * 128; p += gs) {           // p = k*128 + jj
        int k = p >> 7, jj = p & 127;
        g_W1p[p] = make_float2(W1[jj * HDIM + k], W1[(jj + 128) * HDIM + k]);
        g_W2p[p] = make_float2(W2[jj * HDIM + k], W2[(jj + 128) * HDIM + k]);
    }
    for (int p = i0; p < IDIM * 512; p += gs) {           // p = k*512 + q*128 + jj
        int k = p >> 9, r = p & 511, q = r >> 7, jj = r & 127;
        int j0 = q * 256 + jj;
        g_Wihp[p] = make_float2(Wih[j0 * IDIM + k], Wih[(j0 + 128) * IDIM + k]);
    }
    for (int p = i0; p < HDIM * 512; p += gs) {
        int k = p >> 9, r = p & 511, q = r >> 7, jj = r & 127;
        int j0 = q * 256 + jj;
        g_Whhp[p] = make_float2(Whh[j0 * HDIM + k], Whh[(j0 + 128) * HDIM + k]);
    }
}

// --- packed fp32x2 FMA (sm_100+): d = a*b + d ---
__device__ __forceinline__ void ffma2(float2& d, float2 a, float2 b) {
    asm("fma.rn.f32x2 %0, %1, %2, %0;"
        : "+l"(*reinterpret_cast<unsigned long long*>(&d))
        : "l"(*reinterpret_cast<const unsigned long long*>(&a)),
          "l"(*reinterpret_cast<const unsigned long long*>(&b)));
}

__device__ __forceinline__ float4 LD4(const float* p) { return *reinterpret_cast<const float4*>(p); }
__device__ __forceinline__ void  ST4(float* p, float4 v) { *reinterpret_cast<float4*>(p) = v; }
__device__ __forceinline__ float sigm(float x) { return 1.0f / (1.0f + expf(-x)); }

// GEMM core: thread computes 2 columns (Wc pre-offset by jj; pair = (jj, jj+128))
// over 8 rows (aoff..aoff+7).
//   acc[0..3]: col jj,      m-pairs (aoff+2p, aoff+2p+1)
//   acc[4..7]: col jj+128,  same rows
// inT: smem [K][ST]; Wc: global packed float2, row stride RW (in float2).
// Double-buffered prefetch of weight+activation chunks of 4 k.
template<int K, int RW>
__device__ __forceinline__ void gemm2(const float* __restrict__ inT,
                                      const float2* __restrict__ Wc,
                                      int aoff, float2 acc[8]) {
    const float* ap = inT + aoff;
    float2 w0[4], w1[4];
    float4 a0[8], a1[8];
#pragma unroll
    for (int i = 0; i < 4; i++) {
        w0[i] = Wc[i * RW];
        a0[2 * i]     = LD4(ap + i * ST);
        a0[2 * i + 1] = LD4(ap + i * ST + 4);
    }
#pragma unroll 1
    for (int k0 = 0; k0 < K; k0 += 8) {
        // prefetch k0+4..k0+7 into buf1 (always in range: k0+7 <= K-1)
        {
            const float2* wn = Wc + (k0 + 4) * RW;
            const float*  an = ap + (k0 + 4) * ST;
#pragma unroll
            for (int i = 0; i < 4; i++) {
                w1[i] = wn[i * RW];
                a1[2 * i]     = LD4(an + i * ST);
                a1[2 * i + 1] = LD4(an + i * ST + 4);
            }
        }
        // compute buf0 (k0..k0+3)
#pragma unroll
        for (int i = 0; i < 4; i++) {
            float2 wx = make_float2(w0[i].x, w0[i].x);
            float2 wy = make_float2(w0[i].y, w0[i].y);
            float4 lo = a0[2 * i], hi = a0[2 * i + 1];
            ffma2(acc[0], make_float2(lo.x, lo.y), wx);
            ffma2(acc[1], make_float2(lo.z, lo.w), wx);
            ffma2(acc[2], make_float2(hi.x, hi.y), wx);
            ffma2(acc[3], make_float2(hi.z, hi.w), wx);
            ffma2(acc[4], make_float2(lo.x, lo.y), wy);
            ffma2(acc[5], make_float2(lo.z, lo.w), wy);
            ffma2(acc[6], make_float2(hi.x, hi.y), wy);
            ffma2(acc[7], make_float2(hi.z, hi.w), wy);
        }
        // prefetch k0+8..k0+11 into buf0 (guarded; dummy re-read of chunk 0 on last)
        {
            const float2* wn = (k0 + 8 < K) ? Wc + (k0 + 8) * RW : Wc;
            const float*  an = (k0 + 8 < K) ? ap + (k0 + 8) * ST : ap;
#pragma unroll
            for (int i = 0; i < 4; i++) {
                w0[i] = wn[i * RW];
                a0[2 * i]     = LD4(an + i * ST);
                a0[2 * i + 1] = LD4(an + i * ST + 4);
            }
        }
        // compute buf1 (k0+4..k0+7)
#pragma unroll
        for (int i = 0; i < 4; i++) {
            float2 wx = make_float2(w1[i].x, w1[i].x);
            float2 wy = make_float2(w1[i].y, w1[i].y);
            float4 lo = a1[2 * i], hi = a1[2 * i + 1];
            ffma2(acc[0], make_float2(lo.x, lo.y), wx);
            ffma2(acc[1], make_float2(lo.z, lo.w), wx);
            ffma2(acc[2], make_float2(hi.x, hi.y), wx);
            ffma2(acc[3], make_float2(hi.z, hi.w), wx);
            ffma2(acc[4], make_float2(lo.x, lo.y), wy);
            ffma2(acc[5], make_float2(lo.z, lo.w), wy);
            ffma2(acc[6], make_float2(hi.x, hi.y), wy);
            ffma2(acc[7], make_float2(hi.z, hi.w), wy);
        }
    }
}

// one evaluation of f: out = tanh(in @ W1^T + b1) @ W2^T + b2
// ACCH: accumulate h += dt * (11/84) * f(in) instead of plain write.
template<bool ACCH>
__device__ __forceinline__ void feval(const float* __restrict__ inT,
                                      float* __restrict__ outT,
                                      float* __restrict__ Tb,
                                      const float* __restrict__ dt8,
                                      int jj, int aoff,
                                      float b1a, float b1b, float b2a, float b2b) {
    float2 acc[8];
#pragma unroll
    for (int i = 0; i < 8; i++) acc[i] = make_float2(0.f, 0.f);
    gemm2<HDIM, 128>(inT, g_W1p + jj, aoff, acc);
    {
        float* tw0 = Tb + jj * ST + aoff;
        float* tw1 = Tb + (jj + 128) * ST + aoff;
#pragma unroll
        for (int p = 0; p < 4; p++) {
            tw0[2 * p]     = tanhf(acc[p].x + b1a);
            tw0[2 * p + 1] = tanhf(acc[p].y + b1a);
            tw1[2 * p]     = tanhf(acc[4 + p].x + b1b);
            tw1[2 * p + 1] = tanhf(acc[4 + p].y + b1b);
        }
    }
    __syncthreads();
#pragma unroll
    for (int i = 0; i < 8; i++) acc[i] = make_float2(0.f, 0.f);
    gemm2<HDIM, 128>(Tb, g_W2p + jj, aoff, acc);
    {
        float* ow0 = outT + jj * ST + aoff;
        float* ow1 = outT + (jj + 128) * ST + aoff;
        if (ACCH) {
            const float C6 = (float)(11.0 / 84.0);
#pragma unroll
            for (int p = 0; p < 4; p++) {
                ow0[2 * p]     += dt8[2 * p]     * C6 * (acc[p].x + b2a);
                ow0[2 * p + 1] += dt8[2 * p + 1] * C6 * (acc[p].y + b2a);
                ow1[2 * p]     += dt8[2 * p]     * C6 * (acc[4 + p].x + b2b);
                ow1[2 * p + 1] += dt8[2 * p + 1] * C6 * (acc[4 + p].y + b2b);
            }
        } else {
#pragma unroll
            for (int p = 0; p < 4; p++) {
                ow0[2 * p]     = acc[p].x + b2a;
                ow0[2 * p + 1] = acc[p].y + b2a;
                ow1[2 * p]     = acc[4 + p].x + b2b;
                ow1[2 * p + 1] = acc[4 + p].y + b2b;
            }
        }
    }
    __syncthreads();
}

#define BUF (HDIM * ST)  // 5120 floats per state buffer
#define SMEM_FLOATS (8 * BUF + IDIM * ST + MT)
#define SMEM_BYTES  (SMEM_FLOATS * 4)

__global__ void __launch_bounds__(256, 1)
ode_lstm_kernel(const float* __restrict__ x,  const float* __restrict__ h0,
                const float* __restrict__ c0, const float* __restrict__ ts,
                const float* __restrict__ b_ih, const float* __restrict__ b_hh,
                const float* __restrict__ b1,   const float* __restrict__ b2,
                float* __restrict__ out) {
    extern __shared__ float s[];
    float* Hs = s;
    float* K1 = s + 1 * BUF;
    float* K2 = s + 2 * BUF;
    float* K3 = s + 3 * BUF;
    float* K4 = s + 4 * BUF;
    float* K5 = s + 5 * BUF;
    float* As = s + 6 * BUF;
    float* Tb = s + 7 * BUF;
    float* XT = s + 8 * BUF;          // [128][ST]
    float* DT = XT + IDIM * ST;       // [MT]

    const int t = threadIdx.x;
    const int rowBase = blockIdx.x * MT;

    // GEMM thread mapping: 2 columns x 8 rows per thread
    const int jj   = t & 127;
    const int aoff = (t >> 7) * 8;

    // ---- loads (coalesced across t) ----
#pragma unroll
    for (int m = 0; m < MT; m++)
        Hs[t * ST + m] = h0[(size_t)(rowBase + m) * HDIM + t];
    if (t < IDIM) {
#pragma unroll
        for (int m = 0; m < MT; m++)
            XT[t * ST + m] = x[(size_t)(rowBase + m) * IDIM + t];
    }
    if (t < MT) DT[t] = ts[rowBase + t] * (1.0f / NSTEPS);
    const float b1a = b1[jj], b1b = b1[jj + 128];
    const float b2a = b2[jj], b2b = b2[jj + 128];
    __syncthreads();

    float dtm[MT];
#pragma unroll
    for (int m = 0; m < MT; m++) dtm[m] = DT[m];
    float dt8[8];
#pragma unroll
    for (int i = 0; i < 8; i++) dt8[i] = DT[aoff + i];

    // dopri5 tableau
    const float A21 = 0.2f;
    const float A31 = 0.075f, A32 = 0.225f;
    const float A41 = (float)(44.0 / 45.0), A42 = (float)(-56.0 / 15.0), A43 = (float)(32.0 / 9.0);
    const float A51 = (float)(19372.0 / 6561.0), A52 = (float)(-25360.0 / 2187.0),
                A53 = (float)(64448.0 / 6561.0), A54 = (float)(-212.0 / 729.0);
    const float A61 = (float)(9017.0 / 3168.0), A62 = (float)(-355.0 / 33.0),
                A63 = (float)(46732.0 / 5247.0), A64 = (float)(49.0 / 176.0),
                A65 = (float)(-5103.0 / 18656.0);
    const float C1 = (float)(35.0 / 384.0), C3 = (float)(500.0 / 1113.0),
                C4 = (float)(125.0 / 192.0), C5 = (float)(-2187.0 / 6784.0);

    const int b = t * ST;   // elementwise-phase mapping: thread t = column t, rows 0..15

    // ================= ODE: 8 RK45 steps =================
#pragma unroll 1
    for (int step = 0; step < NSTEPS; step++) {
        // k1 = f(h)
        feval<false>(Hs, K1, Tb, dt8, jj, aoff, b1a, b1b, b2a, b2b);

        // A = h + dt*a21*k1
#pragma unroll
        for (int q = 0; q < 4; q++) {
            float h4[4], k1v[4], av[4];
            *(float4*)h4  = LD4(Hs + b + 4 * q);
            *(float4*)k1v = LD4(K1 + b + 4 * q);
#pragma unroll
            for (int c = 0; c < 4; c++)
                av[c] = h4[c] + dtm[4 * q + c] * (A21 * k1v[c]);
            ST4(As + b + 4 * q, *(float4*)av);
        }
        __syncthreads();
        feval<false>(As, K2, Tb, dt8, jj, aoff, b1a, b1b, b2a, b2b);

        // A = h + dt*(a31 k1 + a32 k2)
#pragma unroll
        for (int q = 0; q < 4; q++) {
            float h4[4], k1v[4], k2v[4], av[4];
            *(float4*)h4  = LD4(Hs + b + 4 * q);
            *(float4*)k1v = LD4(K1 + b + 4 * q);
            *(float4*)k2v = LD4(K2 + b + 4 * q);
#pragma unroll
            for (int c = 0; c < 4; c++)
                av[c] = h4[c] + dtm[4 * q + c] * (A31 * k1v[c] + A32 * k2v[c]);
            ST4(As + b + 4 * q, *(float4*)av);
        }
        __syncthreads();
        feval<false>(As, K3, Tb, dt8, jj, aoff, b1a, b1b, b2a, b2b);

        // A = h + dt*(a41 k1 + a42 k2 + a43 k3)
#pragma unroll
        for (int q = 0; q < 4; q++) {
            float h4[4], k1v[4], k2v[4], k3v[4], av[4];
            *(float4*)h4  = LD4(Hs + b + 4 * q);
            *(float4*)k1v = LD4(K1 + b + 4 * q);
            *(float4*)k2v = LD4(K2 + b + 4 * q);
            *(float4*)k3v = LD4(K3 + b + 4 * q);
#pragma unroll
            for (int c = 0; c < 4; c++)
                av[c] = h4[c] + dtm[4 * q + c] *
                        (A41 * k1v[c] + A42 * k2v[c] + A43 * k3v[c]);
            ST4(As + b + 4 * q, *(float4*)av);
        }
        __syncthreads();
        feval<false>(As, K4, Tb, dt8, jj, aoff, b1a, b1b, b2a, b2b);

        // A = h + dt*(a51 k1 + a52 k2 + a53 k3 + a54 k4)
#pragma unroll
        for (int q = 0; q < 4; q++) {
            float h4[4], k1v[4], k2v[4], k3v[4], k4v[4], av[4];
            *(float4*)h4  = LD4(Hs + b + 4 * q);
            *(float4*)k1v = LD4(K1 + b + 4 * q);
            *(float4*)k2v = LD4(K2 + b + 4 * q);
            *(float4*)k3v = LD4(K3 + b + 4 * q);
            *(float4*)k4v = LD4(K4 + b + 4 * q);
#pragma unroll
            for (int c = 0; c < 4; c++)
                av[c] = h4[c] + dtm[4 * q + c] *
                        (A51 * k1v[c] + A52 * k2v[c] + A53 * k3v[c] + A54 * k4v[c]);
            ST4(As + b + 4 * q, *(float4*)av);
        }
        __syncthreads();
        feval<false>(As, K5, Tb, dt8, jj, aoff, b1a, b1b, b2a, b2b);

        // A = h + dt*(a61..a65 · k);  h = h + dt*(c1 k1 + c3 k3 + c4 k4 + c5 k5)
#pragma unroll
        for (int q = 0; q < 4; q++) {
            float h4[4], k1v[4], k2v[4], k3v[4], k4v[4], k5v[4], av[4], hn[4];
            *(float4*)h4  = LD4(Hs + b + 4 * q);
            *(float4*)k1v = LD4(K1 + b + 4 * q);
            *(float4*)k2v = LD4(K2 + b + 4 * q);
            *(float4*)k3v = LD4(K3 + b + 4 * q);
            *(float4*)k4v = LD4(K4 + b + 4 * q);
            *(float4*)k5v = LD4(K5 + b + 4 * q);
#pragma unroll
            for (int c = 0; c < 4; c++) {
                float d = dtm[4 * q + c];
                av[c] = h4[c] + d * (A61 * k1v[c] + A62 * k2v[c] + A63 * k3v[c] +
                                     A64 * k4v[c] + A65 * k5v[c]);
                hn[c] = h4[c] + d * (C1 * k1v[c] + C3 * k3v[c] + C4 * k4v[c] + C5 * k5v[c]);
            }
            ST4(As + b + 4 * q, *(float4*)av);
            ST4(Hs + b + 4 * q, *(float4*)hn);
        }
        __syncthreads();
        // k6 = f(A); h += dt*(11/84)*k6  (fused epilogue)
        feval<true>(As, Hs, Tb, dt8, jj, aoff, b1a, b1b, b2a, b2b);
    }

    // ================= two weight-shared LSTM cells =================
    float* Cs = K5;  // alias free buffers
    float* G0 = K1; float* G1 = K2; float* G2 = K3; float* G3 = K4;

#pragma unroll
    for (int m = 0; m < MT; m++)
        Cs[t * ST + m] = c0[(size_t)(rowBase + m) * HDIM + t];
    __syncthreads();

#pragma unroll 1
    for (int cell = 0; cell < 2; cell++) {
#pragma unroll 1
        for (int q = 0; q < 4; q++) {
            float2 acc[8];
#pragma unroll
            for (int i = 0; i < 8; i++) acc[i] = make_float2(0.f, 0.f);
            gemm2<IDIM, 512>(XT, g_Wihp + q * 128 + jj, aoff, acc);
            gemm2<HDIM, 512>(Hs, g_Whhp + q * 128 + jj, aoff, acc);
            const float bza = b_ih[q * 256 + jj]       + b_hh[q * 256 + jj];
            const float bzb = b_ih[q * 256 + jj + 128] + b_hh[q * 256 + jj + 128];
            float* Gq = (q == 0) ? G0 : (q == 1) ? G1 : (q == 2) ? G2 : G3;
            float* g0 = Gq + jj * ST + aoff;
            float* g1 = Gq + (jj + 128) * ST + aoff;
#pragma unroll
            for (int p = 0; p < 4; p++) {
                float vx0 = acc[p].x + bza,     vy0 = acc[p].y + bza;
                float vx1 = acc[4 + p].x + bzb, vy1 = acc[4 + p].y + bzb;
                if (q == 2) {
                    g0[2 * p] = tanhf(vx0); g0[2 * p + 1] = tanhf(vy0);
                    g1[2 * p] = tanhf(vx1); g1[2 * p + 1] = tanhf(vy1);
                } else {
                    g0[2 * p] = sigm(vx0); g0[2 * p + 1] = sigm(vy0);
                    g1[2 * p] = sigm(vx1); g1[2 * p + 1] = sigm(vy1);
                }
            }
        }
        __syncthreads();
#pragma unroll
        for (int m = 0; m < MT; m++) {
            float iv = G0[b + m], fv = G1[b + m], gv = G2[b + m], ov = G3[b + m];
            float cn = fv * Cs[b + m] + iv * gv;
            Cs[b + m] = cn;
            Hs[b + m] = ov * tanhf(cn);
        }
        __syncthreads();
    }

    // ---- store h2 then c2 (coalesced) ----
    const size_t BH = (size_t)B_TOTAL * HDIM;
#pragma unroll
    for (int m = 0; m < MT; m++) {
        out[(size_t)(rowBase + m) * HDIM + t]      = Hs[t * ST + m];
        out[BH + (size_t)(rowBase + m) * HDIM + t] = Cs[t * ST + m];
    }
}

extern "C" void kernel_launch(void* const* d_in, const int* in_sizes, int n_in,
                              void* d_out, int out_size) {
    const float* x    = (const float*)d_in[0];
    const float* h0   = (const float*)d_in[1];
    const float* c0   = (const float*)d_in[2];
    const float* ts   = (const float*)d_in[3];
    const float* W_ih = (const float*)d_in[4];
    const float* W_hh = (const float*)d_in[5];
    const float* b_ih = (const float*)d_in[6];
    const float* b_hh = (const float*)d_in[7];
    const float* W1   = (const float*)d_in[8];
    const float* b1   = (const float*)d_in[9];
    const float* W2   = (const float*)d_in[10];
    const float* b2   = (const float*)d_in[11];
    float* out = (float*)d_out;

    cudaFuncSetAttribute(ode_lstm_kernel,
                         cudaFuncAttributeMaxDynamicSharedMemorySize, SMEM_BYTES);

    prep_kernel<<<512, 256>>>(W1, W2, W_ih, W_hh);
    ode_lstm_kernel<<<B_TOTAL / MT, 256, SMEM_BYTES>>>(
        x, h0, c0, ts, b_ih, b_hh, b1, b2, out);
}

// round 6
// speedup vs baseline: 1.2916x; 1.2916x over previous
#include <cuda_runtime.h>
#include <math.h>
#include <stdint.h>

// ----------------------------------------------------------------------------
// ODELSTMCell: B=16384, I=128, H=256
//   ODE: 8 fixed RK45 (dopri5) steps of f(h)=tanh(h@W1^T+b1)@W2^T+b2,
//   then two weight-shared LSTM cells.
// R6: persistent-tile CTA (MT=16 rows, 1024 CTAs), state in SMEM transposed
// [256][ST]. 512 threads/CTA. GEMM tiling TJ=2 x TM=4: thread (jj=t&127,
// rq=t>>7) computes columns {jj, jj+128} for rows [4rq, 4rq+4). Per k:
//   1 coalesced LDG.64 (float2-packed weights) + 1 broadcast LDS.128 + 4 FFMA2
// 16 warps/SM (vs 8 in R4/R5) to close the latency-exposure gap; shallow
// weight-only prefetch + inline activation loads for short dep chains.
// ----------------------------------------------------------------------------

#define B_TOTAL 16384
#define HDIM    256
#define IDIM    128
#define MT      16     // batch rows per CTA  (16384 / 16 = 1024 CTAs)
#define ST      20     // smem row stride in floats (mult of 4 for LDS.128)
#define NSTEPS  8
#define TPB     512

// --- packed transposed weight scratch ---
// g_W1p[k*128 + jj] = ( W1[jj][k], W1[jj+128][k] )          [256][128] float2
// g_W2p same layout.
// g_Wihp[k*512 + q*128 + jj] = ( Wih[q*256+jj][k], Wih[q*256+jj+128][k] )
// g_Whhp[k*512 + q*128 + jj] = ( Whh[q*256+jj][k], Whh[q*256+jj+128][k] )
__device__ float2 g_W1p [HDIM * 128];
__device__ float2 g_W2p [HDIM * 128];
__device__ float2 g_Wihp[IDIM * 512];
__device__ float2 g_Whhp[HDIM * 512];

__global__ void prep_kernel(const float* __restrict__ W1, const float* __restrict__ W2,
                            const float* __restrict__ Wih, const float* __restrict__ Whh) {
    int i0 = blockIdx.x * blockDim.x + threadIdx.x;
    int gs = gridDim.x * blockDim.x;
    for (int p = i0; p < HDIM * 128; p += gs) {           // p = k*128 + jj
        int k = p >> 7, jj = p & 127;
        g_W1p[p] = make_float2(W1[jj * HDIM + k], W1[(jj + 128) * HDIM + k]);
        g_W2p[p] = make_float2(W2[jj * HDIM + k], W2[(jj + 128) * HDIM + k]);
    }
    for (int p = i0; p < IDIM * 512; p += gs) {           // p = k*512 + q*128 + jj
        int k = p >> 9, r = p & 511, q = r >> 7, jj = r & 127;
        int j0 = q * 256 + jj;
        g_Wihp[p] = make_float2(Wih[j0 * IDIM + k], Wih[(j0 + 128) * IDIM + k]);
    }
    for (int p = i0; p < HDIM * 512; p += gs) {
        int k = p >> 9, r = p & 511, q = r >> 7, jj = r & 127;
        int j0 = q * 256 + jj;
        g_Whhp[p] = make_float2(Whh[j0 * HDIM + k], Whh[(j0 + 128) * HDIM + k]);
    }
}

// --- packed fp32x2 FMA (sm_100+): d = a*b + d ---
__device__ __forceinline__ void ffma2(float2& d, float2 a, float2 b) {
    asm("fma.rn.f32x2 %0, %1, %2, %0;"
        : "+l"(*reinterpret_cast<unsigned long long*>(&d))
        : "l"(*reinterpret_cast<const unsigned long long*>(&a)),
          "l"(*reinterpret_cast<const unsigned long long*>(&b)));
}

__device__ __forceinline__ float4 LD4(const float* p) { return *reinterpret_cast<const float4*>(p); }
__device__ __forceinline__ void  ST4(float* p, float4 v) { *reinterpret_cast<float4*>(p) = v; }
__device__ __forceinline__ float sigm(float x) { return 1.0f / (1.0f + expf(-x)); }

// GEMM core: thread computes 2 columns (Wc pre-offset by jj; pair (jj, jj+128))
// over 4 rows starting at inA (= inT + 4*rq).
//   acc[0..1]: col jj     (row pairs 0-1, 2-3)
//   acc[2..3]: col jj+128 (same rows)
// inA: smem [K][ST] (pre-offset); Wc: global packed float2, row stride RW.
// Weight-only prefetch (chunk of 8 k); activation LDS.128 inline per k.
template<int K, int RW>
__device__ __forceinline__ void gemm2(const float* __restrict__ inA,
                                      const float2* __restrict__ Wc,
                                      float2 acc[4]) {
    const float2* wp = Wc;
    float2 w[8];
#pragma unroll
    for (int i = 0; i < 8; i++) w[i] = wp[i * RW];
#pragma unroll 1
    for (int k0 = 0; k0 < K; k0 += 8) {
        const float2* wnp = (k0 + 8 < K) ? (wp + 8 * RW) : Wc;  // dummy on last
        float2 wn[8];
#pragma unroll
        for (int i = 0; i < 8; i++) wn[i] = wnp[i * RW];
#pragma unroll
        for (int i = 0; i < 8; i++) {
            float4 a = LD4(inA + (k0 + i) * ST);
            float2 al = make_float2(a.x, a.y);
            float2 ah = make_float2(a.z, a.w);
            float2 wx = make_float2(w[i].x, w[i].x);
            float2 wy = make_float2(w[i].y, w[i].y);
            ffma2(acc[0], al, wx);
            ffma2(acc[1], ah, wx);
            ffma2(acc[2], al, wy);
            ffma2(acc[3], ah, wy);
        }
#pragma unroll
        for (int i = 0; i < 8; i++) w[i] = wn[i];
        wp += 8 * RW;
    }
}

// one evaluation of f: out = tanh(in @ W1^T + b1) @ W2^T + b2
// ACCH: accumulate h += dt * (11/84) * f(in) instead of plain write.
template<bool ACCH>
__device__ __forceinline__ void feval(const float* __restrict__ inT,
                                      float* __restrict__ outT,
                                      float* __restrict__ Tb,
                                      const float* __restrict__ dt4,
                                      int jj, int aoff,
                                      float b1a, float b1b, float b2a, float b2b) {
    float2 acc[4];
#pragma unroll
    for (int i = 0; i < 4; i++) acc[i] = make_float2(0.f, 0.f);
    gemm2<HDIM, 128>(inT + aoff, g_W1p + jj, acc);
    {
        float4 v0 = make_float4(tanhf(acc[0].x + b1a), tanhf(acc[0].y + b1a),
                                tanhf(acc[1].x + b1a), tanhf(acc[1].y + b1a));
        float4 v1 = make_float4(tanhf(acc[2].x + b1b), tanhf(acc[2].y + b1b),
                                tanhf(acc[3].x + b1b), tanhf(acc[3].y + b1b));
        ST4(Tb + jj * ST + aoff, v0);
        ST4(Tb + (jj + 128) * ST + aoff, v1);
    }
    __syncthreads();
#pragma unroll
    for (int i = 0; i < 4; i++) acc[i] = make_float2(0.f, 0.f);
    gemm2<HDIM, 128>(Tb + aoff, g_W2p + jj, acc);
    {
        float* ow0 = outT + jj * ST + aoff;
        float* ow1 = outT + (jj + 128) * ST + aoff;
        if (ACCH) {
            const float C6 = (float)(11.0 / 84.0);
            float4 h0v = LD4(ow0), h1v = LD4(ow1);
            h0v.x += dt4[0] * C6 * (acc[0].x + b2a);
            h0v.y += dt4[1] * C6 * (acc[0].y + b2a);
            h0v.z += dt4[2] * C6 * (acc[1].x + b2a);
            h0v.w += dt4[3] * C6 * (acc[1].y + b2a);
            h1v.x += dt4[0] * C6 * (acc[2].x + b2b);
            h1v.y += dt4[1] * C6 * (acc[2].y + b2b);
            h1v.z += dt4[2] * C6 * (acc[3].x + b2b);
            h1v.w += dt4[3] * C6 * (acc[3].y + b2b);
            ST4(ow0, h0v);
            ST4(ow1, h1v);
        } else {
            ST4(ow0, make_float4(acc[0].x + b2a, acc[0].y + b2a,
                                 acc[1].x + b2a, acc[1].y + b2a));
            ST4(ow1, make_float4(acc[2].x + b2b, acc[2].y + b2b,
                                 acc[3].x + b2b, acc[3].y + b2b));
        }
    }
    __syncthreads();
}

#define BUF (HDIM * ST)  // 5120 floats per state buffer
#define SMEM_FLOATS (8 * BUF + IDIM * ST + MT)
#define SMEM_BYTES  (SMEM_FLOATS * 4)

__global__ void __launch_bounds__(TPB, 1)
ode_lstm_kernel(const float* __restrict__ x,  const float* __restrict__ h0,
                const float* __restrict__ c0, const float* __restrict__ ts,
                const float* __restrict__ b_ih, const float* __restrict__ b_hh,
                const float* __restrict__ b1,   const float* __restrict__ b2,
                float* __restrict__ out) {
    extern __shared__ float s[];
    float* Hs = s;
    float* K1 = s + 1 * BUF;
    float* K2 = s + 2 * BUF;
    float* K3 = s + 3 * BUF;
    float* K4 = s + 4 * BUF;
    float* K5 = s + 5 * BUF;
    float* As = s + 6 * BUF;
    float* Tb = s + 7 * BUF;
    float* XT = s + 8 * BUF;          // [128][ST]
    float* DT = XT + IDIM * ST;       // [MT]

    const int t = threadIdx.x;
    const int rowBase = blockIdx.x * MT;

    // GEMM mapping: 2 columns x 4 rows per thread
    const int jj   = t & 127;
    const int rq   = t >> 7;          // 0..3
    const int aoff = rq * 4;

    // Elementwise mapping: 1 column x 8 rows per thread
    const int colE = t & 255;
    const int eoff = (t >> 8) * 8;    // 0 or 8
    const int b    = colE * ST + eoff;

    // ---- loads (coalesced across t) ----
#pragma unroll
    for (int m = 0; m < 8; m++)
        Hs[b + m] = h0[(size_t)(rowBase + eoff + m) * HDIM + colE];
    {
        int cX = t & 127, q4 = t >> 7;   // q4 in 0..3 -> 4 rows each
#pragma unroll
        for (int m = 0; m < 4; m++)
            XT[cX * ST + q4 * 4 + m] = x[(size_t)(rowBase + q4 * 4 + m) * IDIM + cX];
    }
    if (t < MT) DT[t] = ts[rowBase + t] * (1.0f / NSTEPS);
    const float b1a = b1[jj], b1b = b1[jj + 128];
    const float b2a = b2[jj], b2b = b2[jj + 128];
    __syncthreads();

    float dte[8];                      // dt for elementwise rows
#pragma unroll
    for (int i = 0; i < 8; i++) dte[i] = DT[eoff + i];
    float dt4[4];                      // dt for GEMM rows
#pragma unroll
    for (int i = 0; i < 4; i++) dt4[i] = DT[aoff + i];

    // dopri5 tableau
    const float A21 = 0.2f;
    const float A31 = 0.075f, A32 = 0.225f;
    const float A41 = (float)(44.0 / 45.0), A42 = (float)(-56.0 / 15.0), A43 = (float)(32.0 / 9.0);
    const float A51 = (float)(19372.0 / 6561.0), A52 = (float)(-25360.0 / 2187.0),
                A53 = (float)(64448.0 / 6561.0), A54 = (float)(-212.0 / 729.0);
    const float A61 = (float)(9017.0 / 3168.0), A62 = (float)(-355.0 / 33.0),
                A63 = (float)(46732.0 / 5247.0), A64 = (float)(49.0 / 176.0),
                A65 = (float)(-5103.0 / 18656.0);
    const float C1 = (float)(35.0 / 384.0), C3 = (float)(500.0 / 1113.0),
                C4 = (float)(125.0 / 192.0), C5 = (float)(-2187.0 / 6784.0);

    // ================= ODE: 8 RK45 steps =================
#pragma unroll 1
    for (int step = 0; step < NSTEPS; step++) {
        // k1 = f(h)
        feval<false>(Hs, K1, Tb, dt4, jj, aoff, b1a, b1b, b2a, b2b);

        // A = h + dt*a21*k1
#pragma unroll
        for (int q = 0; q < 2; q++) {
            float h4[4], k1v[4], av[4];
            *(float4*)h4  = LD4(Hs + b + 4 * q);
            *(float4*)k1v = LD4(K1 + b + 4 * q);
#pragma unroll
            for (int c = 0; c < 4; c++)
                av[c] = h4[c] + dte[4 * q + c] * (A21 * k1v[c]);
            ST4(As + b + 4 * q, *(float4*)av);
        }
        __syncthreads();
        feval<false>(As, K2, Tb, dt4, jj, aoff, b1a, b1b, b2a, b2b);

        // A = h + dt*(a31 k1 + a32 k2)
#pragma unroll
        for (int q = 0; q < 2; q++) {
            float h4[4], k1v[4], k2v[4], av[4];
            *(float4*)h4  = LD4(Hs + b + 4 * q);
            *(float4*)k1v = LD4(K1 + b + 4 * q);
            *(float4*)k2v = LD4(K2 + b + 4 * q);
#pragma unroll
            for (int c = 0; c < 4; c++)
                av[c] = h4[c] + dte[4 * q + c] * (A31 * k1v[c] + A32 * k2v[c]);
            ST4(As + b + 4 * q, *(float4*)av);
        }
        __syncthreads();
        feval<false>(As, K3, Tb, dt4, jj, aoff, b1a, b1b, b2a, b2b);

        // A = h + dt*(a41 k1 + a42 k2 + a43 k3)
#pragma unroll
        for (int q = 0; q < 2; q++) {
            float h4[4], k1v[4], k2v[4], k3v[4], av[4];
            *(float4*)h4  = LD4(Hs + b + 4 * q);
            *(float4*)k1v = LD4(K1 + b + 4 * q);
            *(float4*)k2v = LD4(K2 + b + 4 * q);
            *(float4*)k3v = LD4(K3 + b + 4 * q);
#pragma unroll
            for (int c = 0; c < 4; c++)
                av[c] = h4[c] + dte[4 * q + c] *
                        (A41 * k1v[c] + A42 * k2v[c] + A43 * k3v[c]);
            ST4(As + b + 4 * q, *(float4*)av);
        }
        __syncthreads();
        feval<false>(As, K4, Tb, dt4, jj, aoff, b1a, b1b, b2a, b2b);

        // A = h + dt*(a51 k1 + a52 k2 + a53 k3 + a54 k4)
#pragma unroll
        for (int q = 0; q < 2; q++) {
            float h4[4], k1v[4], k2v[4], k3v[4], k4v[4], av[4];
            *(float4*)h4  = LD4(Hs + b + 4 * q);
            *(float4*)k1v = LD4(K1 + b + 4 * q);
            *(float4*)k2v = LD4(K2 + b + 4 * q);
            *(float4*)k3v = LD4(K3 + b + 4 * q);
            *(float4*)k4v = LD4(K4 + b + 4 * q);
#pragma unroll
            for (int c = 0; c < 4; c++)
                av[c] = h4[c] + dte[4 * q + c] *
                        (A51 * k1v[c] + A52 * k2v[c] + A53 * k3v[c] + A54 * k4v[c]);
            ST4(As + b + 4 * q, *(float4*)av);
        }
        __syncthreads();
        feval<false>(As, K5, Tb, dt4, jj, aoff, b1a, b1b, b2a, b2b);

        // A = h + dt*(a61..a65 · k);  h = h + dt*(c1 k1 + c3 k3 + c4 k4 + c5 k5)
#pragma unroll
        for (int q = 0; q < 2; q++) {
            float h4[4], k1v[4], k2v[4], k3v[4], k4v[4], k5v[4], av[4], hn[4];
            *(float4*)h4  = LD4(Hs + b + 4 * q);
            *(float4*)k1v = LD4(K1 + b + 4 * q);
            *(float4*)k2v = LD4(K2 + b + 4 * q);
            *(float4*)k3v = LD4(K3 + b + 4 * q);
            *(float4*)k4v = LD4(K4 + b + 4 * q);
            *(float4*)k5v = LD4(K5 + b + 4 * q);
#pragma unroll
            for (int c = 0; c < 4; c++) {
                float d = dte[4 * q + c];
                av[c] = h4[c] + d * (A61 * k1v[c] + A62 * k2v[c] + A63 * k3v[c] +
                                     A64 * k4v[c] + A65 * k5v[c]);
                hn[c] = h4[c] + d * (C1 * k1v[c] + C3 * k3v[c] + C4 * k4v[c] + C5 * k5v[c]);
            }
            ST4(As + b + 4 * q, *(float4*)av);
            ST4(Hs + b + 4 * q, *(float4*)hn);
        }
        __syncthreads();
        // k6 = f(A); h += dt*(11/84)*k6  (fused epilogue)
        feval<true>(As, Hs, Tb, dt4, jj, aoff, b1a, b1b, b2a, b2b);
    }

    // ================= two weight-shared LSTM cells =================
    float* Cs = K5;  // alias free buffers
    float* G0 = K1; float* G1 = K2; float* G2 = K3; float* G3 = K4;

#pragma unroll
    for (int m = 0; m < 8; m++)
        Cs[b + m] = c0[(size_t)(rowBase + eoff + m) * HDIM + colE];
    __syncthreads();

#pragma unroll 1
    for (int cell = 0; cell < 2; cell++) {
#pragma unroll 1
        for (int q = 0; q < 4; q++) {
            float2 acc[4];
#pragma unroll
            for (int i = 0; i < 4; i++) acc[i] = make_float2(0.f, 0.f);
            gemm2<IDIM, 512>(XT + aoff, g_Wihp + q * 128 + jj, acc);
            gemm2<HDIM, 512>(Hs + aoff, g_Whhp + q * 128 + jj, acc);
            const float bza = b_ih[q * 256 + jj]       + b_hh[q * 256 + jj];
            const float bzb = b_ih[q * 256 + jj + 128] + b_hh[q * 256 + jj + 128];
            float* Gq = (q == 0) ? G0 : (q == 1) ? G1 : (q == 2) ? G2 : G3;
            float va[4], vb[4];
            va[0] = acc[0].x + bza; va[1] = acc[0].y + bza;
            va[2] = acc[1].x + bza; va[3] = acc[1].y + bza;
            vb[0] = acc[2].x + bzb; vb[1] = acc[2].y + bzb;
            vb[2] = acc[3].x + bzb; vb[3] = acc[3].y + bzb;
            float4 o0, o1;
            if (q == 2) {
                o0 = make_float4(tanhf(va[0]), tanhf(va[1]), tanhf(va[2]), tanhf(va[3]));
                o1 = make_float4(tanhf(vb[0]), tanhf(vb[1]), tanhf(vb[2]), tanhf(vb[3]));
            } else {
                o0 = make_float4(sigm(va[0]), sigm(va[1]), sigm(va[2]), sigm(va[3]));
                o1 = make_float4(sigm(vb[0]), sigm(vb[1]), sigm(vb[2]), sigm(vb[3]));
            }
            ST4(Gq + jj * ST + aoff, o0);
            ST4(Gq + (jj + 128) * ST + aoff, o1);
        }
        __syncthreads();
#pragma unroll
        for (int m = 0; m < 8; m++) {
            float iv = G0[b + m], fv = G1[b + m], gv = G2[b + m], ov = G3[b + m];
            float cn = fv * Cs[b + m] + iv * gv;
            Cs[b + m] = cn;
            Hs[b + m] = ov * tanhf(cn);
        }
        __syncthreads();
    }

    // ---- store h2 then c2 (coalesced) ----
    const size_t BH = (size_t)B_TOTAL * HDIM;
#pragma unroll
    for (int m = 0; m < 8; m++) {
        out[(size_t)(rowBase + eoff + m) * HDIM + colE]      = Hs[b + m];
        out[BH + (size_t)(rowBase + eoff + m) * HDIM + colE] = Cs[b + m];
    }
}

extern "C" void kernel_launch(void* const* d_in, const int* in_sizes, int n_in,
                              void* d_out, int out_size) {
    const float* x    = (const float*)d_in[0];
    const float* h0   = (const float*)d_in[1];
    const float* c0   = (const float*)d_in[2];
    const float* ts   = (const float*)d_in[3];
    const float* W_ih = (const float*)d_in[4];
    const float* W_hh = (const float*)d_in[5];
    const float* b_ih = (const float*)d_in[6];
    const float* b_hh = (const float*)d_in[7];
    const float* W1   = (const float*)d_in[8];
    const float* b1   = (const float*)d_in[9];
    const float* W2   = (const float*)d_in[10];
    const float* b2   = (const float*)d_in[11];
    float* out = (float*)d_out;

    cudaFuncSetAttribute(ode_lstm_kernel,
                         cudaFuncAttributeMaxDynamicSharedMemorySize, SMEM_BYTES);

    prep_kernel<<<512, 256>>>(W1, W2, W_ih, W_hh);
    ode_lstm_kernel<<<B_TOTAL / MT, TPB, SMEM_BYTES>>>(
        x, h0, c0, ts, b_ih, b_hh, b1, b2, out);
}

// round 7
// speedup vs baseline: 1.5701x; 1.2156x over previous
#include <cuda_runtime.h>
#include <math.h>
#include <stdint.h>

// ----------------------------------------------------------------------------
// ODELSTMCell: B=16384, I=128, H=256
// R7: 256 threads/CTA, MT=16 rows, balanced GEMM tile TJ=2 x TM=8
//   (per k: 1 LDG.64 weights + 2 broadcast LDS.128 acts + 8 FFMA2
//    -> 32 wavefronts : 32 FMA-cyc per CTA per k, 1:1).
// SMEM trimmed to 112 KB (ST=16, Tb aliased onto As, XT reloaded late) so
// TWO CTAs co-reside per SM -> 16 warps/SM for latency hiding (R5's tile
// was wf-optimal but starved at 8 warps; R6 proved 16 warps reach ~49% issue).
// ----------------------------------------------------------------------------

#define B_TOTAL 16384
#define HDIM    256
#define IDIM    128
#define MT      16     // batch rows per CTA  (1024 CTAs)
#define ST      16     // smem row stride in floats (no pad; GEMM reads broadcast)
#define NSTEPS  8
#define TPB     256

// --- packed transposed weight scratch ---
// g_W1p[k*128 + jj] = ( W1[jj][k], W1[jj+128][k] )   [256][128] float2
// g_W2p same. g_Wihp/g_Whhp: [k][q*128+jj] pairs (j0=q*256+jj, j0+128).
__device__ float2 g_W1p [HDIM * 128];
__device__ float2 g_W2p [HDIM * 128];
__device__ float2 g_Wihp[IDIM * 512];
__device__ float2 g_Whhp[HDIM * 512];

__global__ void prep_kernel(const float* __restrict__ W1, const float* __restrict__ W2,
                            const float* __restrict__ Wih, const float* __restrict__ Whh) {
    int i0 = blockIdx.x * blockDim.x + threadIdx.x;
    int gs = gridDim.x * blockDim.x;
    for (int p = i0; p < HDIM * 128; p += gs) {           // p = k*128 + jj
        int k = p >> 7, jj = p & 127;
        g_W1p[p] = make_float2(W1[jj * HDIM + k], W1[(jj + 128) * HDIM + k]);
        g_W2p[p] = make_float2(W2[jj * HDIM + k], W2[(jj + 128) * HDIM + k]);
    }
    for (int p = i0; p < IDIM * 512; p += gs) {           // p = k*512 + q*128 + jj
        int k = p >> 9, r = p & 511, q = r >> 7, jj = r & 127;
        int j0 = q * 256 + jj;
        g_Wihp[p] = make_float2(Wih[j0 * IDIM + k], Wih[(j0 + 128) * IDIM + k]);
    }
    for (int p = i0; p < HDIM * 512; p += gs) {
        int k = p >> 9, r = p & 511, q = r >> 7, jj = r & 127;
        int j0 = q * 256 + jj;
        g_Whhp[p] = make_float2(Whh[j0 * HDIM + k], Whh[(j0 + 128) * HDIM + k]);
    }
}

// --- packed fp32x2 FMA (sm_100+): d = a*b + d ---
__device__ __forceinline__ void ffma2(float2& d, float2 a, float2 b) {
    asm("fma.rn.f32x2 %0, %1, %2, %0;"
        : "+l"(*reinterpret_cast<unsigned long long*>(&d))
        : "l"(*reinterpret_cast<const unsigned long long*>(&a)),
          "l"(*reinterpret_cast<const unsigned long long*>(&b)));
}

__device__ __forceinline__ float4 LD4(const float* p) { return *reinterpret_cast<const float4*>(p); }
__device__ __forceinline__ void  ST4(float* p, float4 v) { *reinterpret_cast<float4*>(p) = v; }
__device__ __forceinline__ float sigm(float x) { return 1.0f / (1.0f + expf(-x)); }

// GEMM core: thread computes 2 columns {jj, jj+128} x 8 rows [aoff, aoff+8).
//   acc[0..3]: col jj     (row pairs)
//   acc[4..7]: col jj+128 (same rows)
// inA: smem [K][ST], pre-offset by aoff; Wc: global packed float2, row stride RW.
// Shallow weight-only prefetch (chunk of 8 k); activation LDS.128 inline.
template<int K, int RW>
__device__ __forceinline__ void gemm2(const float* __restrict__ inA,
                                      const float2* __restrict__ Wc,
                                      float2 acc[8]) {
    const float2* wp = Wc;
    float2 w[8];
#pragma unroll
    for (int i = 0; i < 8; i++) w[i] = wp[i * RW];
#pragma unroll 1
    for (int k0 = 0; k0 < K; k0 += 8) {
        const float2* wnp = (k0 + 8 < K) ? (wp + 8 * RW) : Wc;  // dummy on last
        float2 wn[8];
#pragma unroll
        for (int i = 0; i < 8; i++) wn[i] = wnp[i * RW];
#pragma unroll
        for (int i = 0; i < 8; i++) {
            const float* ap = inA + (k0 + i) * ST;
            float4 a0 = LD4(ap), a1 = LD4(ap + 4);
            float2 wx = make_float2(w[i].x, w[i].x);
            float2 wy = make_float2(w[i].y, w[i].y);
            ffma2(acc[0], make_float2(a0.x, a0.y), wx);
            ffma2(acc[1], make_float2(a0.z, a0.w), wx);
            ffma2(acc[2], make_float2(a1.x, a1.y), wx);
            ffma2(acc[3], make_float2(a1.z, a1.w), wx);
            ffma2(acc[4], make_float2(a0.x, a0.y), wy);
            ffma2(acc[5], make_float2(a0.z, a0.w), wy);
            ffma2(acc[6], make_float2(a1.x, a1.y), wy);
            ffma2(acc[7], make_float2(a1.z, a1.w), wy);
        }
#pragma unroll
        for (int i = 0; i < 8; i++) w[i] = wn[i];
        wp += 8 * RW;
    }
}

// one evaluation of f: out = tanh(in @ W1^T + b1) @ W2^T + b2
// Tb MAY ALIAS in (As): a __syncthreads separates gemm1 reads from Tb writes.
// ACCH: accumulate h += dt * (11/84) * f(in).
template<bool ACCH>
__device__ __forceinline__ void feval(const float* __restrict__ inT,
                                      float* __restrict__ outT,
                                      float* __restrict__ Tb,
                                      const float* __restrict__ dt8,
                                      int jj, int aoff,
                                      float b1a, float b1b, float b2a, float b2b) {
    float2 acc[8];
#pragma unroll
    for (int i = 0; i < 8; i++) acc[i] = make_float2(0.f, 0.f);
    gemm2<HDIM, 128>(inT + aoff, g_W1p + jj, acc);
    __syncthreads();   // all gemm1 reads of inT done before Tb (==inT) writes
    {
        float4 v0 = make_float4(tanhf(acc[0].x + b1a), tanhf(acc[0].y + b1a),
                                tanhf(acc[1].x + b1a), tanhf(acc[1].y + b1a));
        float4 v1 = make_float4(tanhf(acc[2].x + b1a), tanhf(acc[2].y + b1a),
                                tanhf(acc[3].x + b1a), tanhf(acc[3].y + b1a));
        float4 v2 = make_float4(tanhf(acc[4].x + b1b), tanhf(acc[4].y + b1b),
                                tanhf(acc[5].x + b1b), tanhf(acc[5].y + b1b));
        float4 v3 = make_float4(tanhf(acc[6].x + b1b), tanhf(acc[6].y + b1b),
                                tanhf(acc[7].x + b1b), tanhf(acc[7].y + b1b));
        ST4(Tb + jj * ST + aoff, v0);
        ST4(Tb + jj * ST + aoff + 4, v1);
        ST4(Tb + (jj + 128) * ST + aoff, v2);
        ST4(Tb + (jj + 128) * ST + aoff + 4, v3);
    }
    __syncthreads();
#pragma unroll
    for (int i = 0; i < 8; i++) acc[i] = make_float2(0.f, 0.f);
    gemm2<HDIM, 128>(Tb + aoff, g_W2p + jj, acc);
    {
        float* ow0 = outT + jj * ST + aoff;
        float* ow1 = outT + (jj + 128) * ST + aoff;
        if (ACCH) {
            const float C6 = (float)(11.0 / 84.0);
            float4 h0v = LD4(ow0), h1v = LD4(ow0 + 4);
            float4 h2v = LD4(ow1), h3v = LD4(ow1 + 4);
            h0v.x += dt8[0] * C6 * (acc[0].x + b2a);
            h0v.y += dt8[1] * C6 * (acc[0].y + b2a);
            h0v.z += dt8[2] * C6 * (acc[1].x + b2a);
            h0v.w += dt8[3] * C6 * (acc[1].y + b2a);
            h1v.x += dt8[4] * C6 * (acc[2].x + b2a);
            h1v.y += dt8[5] * C6 * (acc[2].y + b2a);
            h1v.z += dt8[6] * C6 * (acc[3].x + b2a);
            h1v.w += dt8[7] * C6 * (acc[3].y + b2a);
            h2v.x += dt8[0] * C6 * (acc[4].x + b2b);
            h2v.y += dt8[1] * C6 * (acc[4].y + b2b);
            h2v.z += dt8[2] * C6 * (acc[5].x + b2b);
            h2v.w += dt8[3] * C6 * (acc[5].y + b2b);
            h3v.x += dt8[4] * C6 * (acc[6].x + b2b);
            h3v.y += dt8[5] * C6 * (acc[6].y + b2b);
            h3v.z += dt8[6] * C6 * (acc[7].x + b2b);
            h3v.w += dt8[7] * C6 * (acc[7].y + b2b);
            ST4(ow0, h0v); ST4(ow0 + 4, h1v);
            ST4(ow1, h2v); ST4(ow1 + 4, h3v);
        } else {
            ST4(ow0,     make_float4(acc[0].x + b2a, acc[0].y + b2a, acc[1].x + b2a, acc[1].y + b2a));
            ST4(ow0 + 4, make_float4(acc[2].x + b2a, acc[2].y + b2a, acc[3].x + b2a, acc[3].y + b2a));
            ST4(ow1,     make_float4(acc[4].x + b2b, acc[4].y + b2b, acc[5].x + b2b, acc[5].y + b2b));
            ST4(ow1 + 4, make_float4(acc[6].x + b2b, acc[6].y + b2b, acc[7].x + b2b, acc[7].y + b2b));
        }
    }
    __syncthreads();
}

#define BUF (HDIM * ST)  // 4096 floats per state buffer
#define SMEM_FLOATS (7 * BUF + MT)
#define SMEM_BYTES  (SMEM_FLOATS * 4)   // 114752 B -> 2 CTAs/SM

__global__ void __launch_bounds__(TPB, 2)
ode_lstm_kernel(const float* __restrict__ x,  const float* __restrict__ h0,
                const float* __restrict__ c0, const float* __restrict__ ts,
                const float* __restrict__ b_ih, const float* __restrict__ b_hh,
                const float* __restrict__ b1,   const float* __restrict__ b2,
                float* __restrict__ out) {
    extern __shared__ float s[];
    float* Hs = s;
    float* K1 = s + 1 * BUF;
    float* K2 = s + 2 * BUF;
    float* K3 = s + 3 * BUF;
    float* K4 = s + 4 * BUF;
    float* K5 = s + 5 * BUF;
    float* AT = s + 6 * BUF;          // As / Tb shared; XT overlay in LSTM phase
    float* DT = s + 7 * BUF;          // [MT]

    const int t = threadIdx.x;
    const int rowBase = blockIdx.x * MT;

    // GEMM mapping: 2 columns x 8 rows per thread
    const int jj   = t & 127;
    const int aoff = (t >> 7) * 8;    // 0 or 8

    // Elementwise mapping: thread t = column t, all 16 rows
    const int b = t * ST;

    // ---- loads (coalesced across t) ----
#pragma unroll
    for (int m = 0; m < MT; m++)
        Hs[b + m] = h0[(size_t)(rowBase + m) * HDIM + t];
    if (t < MT) DT[t] = ts[rowBase + t] * (1.0f / NSTEPS);
    const float b1a = b1[jj], b1b = b1[jj + 128];
    const float b2a = b2[jj], b2b = b2[jj + 128];
    __syncthreads();

    float dtm[MT];
#pragma unroll
    for (int m = 0; m < MT; m++) dtm[m] = DT[m];
    float dt8[8];
#pragma unroll
    for (int i = 0; i < 8; i++) dt8[i] = DT[aoff + i];

    // dopri5 tableau
    const float A21 = 0.2f;
    const float A31 = 0.075f, A32 = 0.225f;
    const float A41 = (float)(44.0 / 45.0), A42 = (float)(-56.0 / 15.0), A43 = (float)(32.0 / 9.0);
    const float A51 = (float)(19372.0 / 6561.0), A52 = (float)(-25360.0 / 2187.0),
                A53 = (float)(64448.0 / 6561.0), A54 = (float)(-212.0 / 729.0);
    const float A61 = (float)(9017.0 / 3168.0), A62 = (float)(-355.0 / 33.0),
                A63 = (float)(46732.0 / 5247.0), A64 = (float)(49.0 / 176.0),
                A65 = (float)(-5103.0 / 18656.0);
    const float C1 = (float)(35.0 / 384.0), C3 = (float)(500.0 / 1113.0),
                C4 = (float)(125.0 / 192.0), C5 = (float)(-2187.0 / 6784.0);

    // ================= ODE: 8 RK45 steps =================
#pragma unroll 1
    for (int step = 0; step < NSTEPS; step++) {
        // k1 = f(h)   (Tb==AT, free here)
        feval<false>(Hs, K1, AT, dt8, jj, aoff, b1a, b1b, b2a, b2b);

        // A = h + dt*a21*k1
#pragma unroll
        for (int q = 0; q < 4; q++) {
            float h4[4], k1v[4], av[4];
            *(float4*)h4  = LD4(Hs + b + 4 * q);
            *(float4*)k1v = LD4(K1 + b + 4 * q);
#pragma unroll
            for (int c = 0; c < 4; c++)
                av[c] = h4[c] + dtm[4 * q + c] * (A21 * k1v[c]);
            ST4(AT + b + 4 * q, *(float4*)av);
        }
        __syncthreads();
        feval<false>(AT, K2, AT, dt8, jj, aoff, b1a, b1b, b2a, b2b);

        // A = h + dt*(a31 k1 + a32 k2)
#pragma unroll
        for (int q = 0; q < 4; q++) {
            float h4[4], k1v[4], k2v[4], av[4];
            *(float4*)h4  = LD4(Hs + b + 4 * q);
            *(float4*)k1v = LD4(K1 + b + 4 * q);
            *(float4*)k2v = LD4(K2 + b + 4 * q);
#pragma unroll
            for (int c = 0; c < 4; c++)
                av[c] = h4[c] + dtm[4 * q + c] * (A31 * k1v[c] + A32 * k2v[c]);
            ST4(AT + b + 4 * q, *(float4*)av);
        }
        __syncthreads();
        feval<false>(AT, K3, AT, dt8, jj, aoff, b1a, b1b, b2a, b2b);

        // A = h + dt*(a41 k1 + a42 k2 + a43 k3)
#pragma unroll
        for (int q = 0; q < 4; q++) {
            float h4[4], k1v[4], k2v[4], k3v[4], av[4];
            *(float4*)h4  = LD4(Hs + b + 4 * q);
            *(float4*)k1v = LD4(K1 + b + 4 * q);
            *(float4*)k2v = LD4(K2 + b + 4 * q);
            *(float4*)k3v = LD4(K3 + b + 4 * q);
#pragma unroll
            for (int c = 0; c < 4; c++)
                av[c] = h4[c] + dtm[4 * q + c] *
                        (A41 * k1v[c] + A42 * k2v[c] + A43 * k3v[c]);
            ST4(AT + b + 4 * q, *(float4*)av);
        }
        __syncthreads();
        feval<false>(AT, K4, AT, dt8, jj, aoff, b1a, b1b, b2a, b2b);

        // A = h + dt*(a51 k1 + a52 k2 + a53 k3 + a54 k4)
#pragma unroll
        for (int q = 0; q < 4; q++) {
            float h4[4], k1v[4], k2v[4], k3v[4], k4v[4], av[4];
            *(float4*)h4  = LD4(Hs + b + 4 * q);
            *(float4*)k1v = LD4(K1 + b + 4 * q);
            *(float4*)k2v = LD4(K2 + b + 4 * q);
            *(float4*)k3v = LD4(K3 + b + 4 * q);
            *(float4*)k4v = LD4(K4 + b + 4 * q);
#pragma unroll
            for (int c = 0; c < 4; c++)
                av[c] = h4[c] + dtm[4 * q + c] *
                        (A51 * k1v[c] + A52 * k2v[c] + A53 * k3v[c] + A54 * k4v[c]);
            ST4(AT + b + 4 * q, *(float4*)av);
        }
        __syncthreads();
        feval<false>(AT, K5, AT, dt8, jj, aoff, b1a, b1b, b2a, b2b);

        // A = h + dt*(a61..a65 · k);  h = h + dt*(c1 k1 + c3 k3 + c4 k4 + c5 k5)
#pragma unroll
        for (int q = 0; q < 4; q++) {
            float h4[4], k1v[4], k2v[4], k3v[4], k4v[4], k5v[4], av[4], hn[4];
            *(float4*)h4  = LD4(Hs + b + 4 * q);
            *(float4*)k1v = LD4(K1 + b + 4 * q);
            *(float4*)k2v = LD4(K2 + b + 4 * q);
            *(float4*)k3v = LD4(K3 + b + 4 * q);
            *(float4*)k4v = LD4(K4 + b + 4 * q);
            *(float4*)k5v = LD4(K5 + b + 4 * q);
#pragma unroll
            for (int c = 0; c < 4; c++) {
                float d = dtm[4 * q + c];
                av[c] = h4[c] + d * (A61 * k1v[c] + A62 * k2v[c] + A63 * k3v[c] +
                                     A64 * k4v[c] + A65 * k5v[c]);
                hn[c] = h4[c] + d * (C1 * k1v[c] + C3 * k3v[c] + C4 * k4v[c] + C5 * k5v[c]);
            }
            ST4(AT + b + 4 * q, *(float4*)av);
            ST4(Hs + b + 4 * q, *(float4*)hn);
        }
        __syncthreads();
        // k6 = f(A); h += dt*(11/84)*k6  (fused epilogue)
        feval<true>(AT, Hs, AT, dt8, jj, aoff, b1a, b1b, b2a, b2b);
    }

    // ================= two weight-shared LSTM cells =================
    float* Cs = K5;  // alias free buffers
    float* G0 = K1; float* G1 = K2; float* G2 = K3; float* G3 = K4;
    float* XT = AT;  // [128][ST] overlay — AT free now; reload x from global

#pragma unroll
    for (int m = 0; m < MT; m++)
        Cs[b + m] = c0[(size_t)(rowBase + m) * HDIM + t];
    if (t < IDIM) {
#pragma unroll
        for (int m = 0; m < MT; m++)
            XT[t * ST + m] = x[(size_t)(rowBase + m) * IDIM + t];
    }
    __syncthreads();

#pragma unroll 1
    for (int cell = 0; cell < 2; cell++) {
#pragma unroll 1
        for (int q = 0; q < 4; q++) {
            float2 acc[8];
#pragma unroll
            for (int i = 0; i < 8; i++) acc[i] = make_float2(0.f, 0.f);
            gemm2<IDIM, 512>(XT + aoff, g_Wihp + q * 128 + jj, acc);
            gemm2<HDIM, 512>(Hs + aoff, g_Whhp + q * 128 + jj, acc);
            const float bza = b_ih[q * 256 + jj]       + b_hh[q * 256 + jj];
            const float bzb = b_ih[q * 256 + jj + 128] + b_hh[q * 256 + jj + 128];
            float* Gq = (q == 0) ? G0 : (q == 1) ? G1 : (q == 2) ? G2 : G3;
            float va[8], vb[8];
#pragma unroll
            for (int p = 0; p < 4; p++) {
                va[2 * p] = acc[p].x + bza;     va[2 * p + 1] = acc[p].y + bza;
                vb[2 * p] = acc[4 + p].x + bzb; vb[2 * p + 1] = acc[4 + p].y + bzb;
            }
            float4 o0, o1, o2, o3;
            if (q == 2) {
                o0 = make_float4(tanhf(va[0]), tanhf(va[1]), tanhf(va[2]), tanhf(va[3]));
                o1 = make_float4(tanhf(va[4]), tanhf(va[5]), tanhf(va[6]), tanhf(va[7]));
                o2 = make_float4(tanhf(vb[0]), tanhf(vb[1]), tanhf(vb[2]), tanhf(vb[3]));
                o3 = make_float4(tanhf(vb[4]), tanhf(vb[5]), tanhf(vb[6]), tanhf(vb[7]));
            } else {
                o0 = make_float4(sigm(va[0]), sigm(va[1]), sigm(va[2]), sigm(va[3]));
                o1 = make_float4(sigm(va[4]), sigm(va[5]), sigm(va[6]), sigm(va[7]));
                o2 = make_float4(sigm(vb[0]), sigm(vb[1]), sigm(vb[2]), sigm(vb[3]));
                o3 = make_float4(sigm(vb[4]), sigm(vb[5]), sigm(vb[6]), sigm(vb[7]));
            }
            ST4(Gq + jj * ST + aoff, o0);
            ST4(Gq + jj * ST + aoff + 4, o1);
            ST4(Gq + (jj + 128) * ST + aoff, o2);
            ST4(Gq + (jj + 128) * ST + aoff + 4, o3);
        }
        __syncthreads();
#pragma unroll
        for (int m = 0; m < MT; m++) {
            float iv = G0[b + m], fv = G1[b + m], gv = G2[b + m], ov = G3[b + m];
            float cn = fv * Cs[b + m] + iv * gv;
            Cs[b + m] = cn;
            Hs[b + m] = ov * tanhf(cn);
        }
        __syncthreads();
    }

    // ---- store h2 then c2 (coalesced) ----
    const size_t BH = (size_t)B_TOTAL * HDIM;
#pragma unroll
    for (int m = 0; m < MT; m++) {
        out[(size_t)(rowBase + m) * HDIM + t]      = Hs[b + m];
        out[BH + (size_t)(rowBase + m) * HDIM + t] = Cs[b + m];
    }
}

extern "C" void kernel_launch(void* const* d_in, const int* in_sizes, int n_in,
                              void* d_out, int out_size) {
    const float* x    = (const float*)d_in[0];
    const float* h0   = (const float*)d_in[1];
    const float* c0   = (const float*)d_in[2];
    const float* ts   = (const float*)d_in[3];
    const float* W_ih = (const float*)d_in[4];
    const float* W_hh = (const float*)d_in[5];
    const float* b_ih = (const float*)d_in[6];
    const float* b_hh = (const float*)d_in[7];
    const float* W1   = (const float*)d_in[8];
    const float* b1   = (const float*)d_in[9];
    const float* W2   = (const float*)d_in[10];
    const float* b2   = (const float*)d_in[11];
    float* out = (float*)d_out;

    cudaFuncSetAttribute(ode_lstm_kernel,
                         cudaFuncAttributeMaxDynamicSharedMemorySize, SMEM_BYTES);

    prep_kernel<<<512, 256>>>(W1, W2, W_ih, W_hh);
    ode_lstm_kernel<<<B_TOTAL / MT, TPB, SMEM_BYTES>>>(
        x, h0, c0, ts, b_ih, b_hh, b1, b2, out);
}

// round 8
// speedup vs baseline: 1.5706x; 1.0004x over previous
#include <cuda_runtime.h>
#include <math.h>
#include <stdint.h>

// ----------------------------------------------------------------------------
// ODELSTMCell: B=16384, I=128, H=256
// R7: 256 threads/CTA, MT=16 rows, balanced GEMM tile TJ=2 x TM=8
//   (per k: 1 LDG.64 weights + 2 broadcast LDS.128 acts + 8 FFMA2
//    -> 32 wavefronts : 32 FMA-cyc per CTA per k, 1:1).
// SMEM trimmed to 112 KB (ST=16, Tb aliased onto As, XT reloaded late) so
// TWO CTAs co-reside per SM -> 16 warps/SM for latency hiding (R5's tile
// was wf-optimal but starved at 8 warps; R6 proved 16 warps reach ~49% issue).
// ----------------------------------------------------------------------------

#define B_TOTAL 16384
#define HDIM    256
#define IDIM    128
#define MT      16     // batch rows per CTA  (1024 CTAs)
#define ST      16     // smem row stride in floats (no pad; GEMM reads broadcast)
#define NSTEPS  8
#define TPB     256

// --- packed transposed weight scratch ---
// g_W1p[k*128 + jj] = ( W1[jj][k], W1[jj+128][k] )   [256][128] float2
// g_W2p same. g_Wihp/g_Whhp: [k][q*128+jj] pairs (j0=q*256+jj, j0+128).
__device__ float2 g_W1p [HDIM * 128];
__device__ float2 g_W2p [HDIM * 128];
__device__ float2 g_Wihp[IDIM * 512];
__device__ float2 g_Whhp[HDIM * 512];

__global__ void prep_kernel(const float* __restrict__ W1, const float* __restrict__ W2,
                            const float* __restrict__ Wih, const float* __restrict__ Whh) {
    int i0 = blockIdx.x * blockDim.x + threadIdx.x;
    int gs = gridDim.x * blockDim.x;
    for (int p = i0; p < HDIM * 128; p += gs) {           // p = k*128 + jj
        int k = p >> 7, jj = p & 127;
        g_W1p[p] = make_float2(W1[jj * HDIM + k], W1[(jj + 128) * HDIM + k]);
        g_W2p[p] = make_float2(W2[jj * HDIM + k], W2[(jj + 128) * HDIM + k]);
    }
    for (int p = i0; p < IDIM * 512; p += gs) {           // p = k*512 + q*128 + jj
        int k = p >> 9, r = p & 511, q = r >> 7, jj = r & 127;
        int j0 = q * 256 + jj;
        g_Wihp[p] = make_float2(Wih[j0 * IDIM + k], Wih[(j0 + 128) * IDIM + k]);
    }
    for (int p = i0; p < HDIM * 512; p += gs) {
        int k = p >> 9, r = p & 511, q = r >> 7, jj = r & 127;
        int j0 = q * 256 + jj;
        g_Whhp[p] = make_float2(Whh[j0 * HDIM + k], Whh[(j0 + 128) * HDIM + k]);
    }
}

// --- packed fp32x2 FMA (sm_100+): d = a*b + d ---
__device__ __forceinline__ void ffma2(float2& d, float2 a, float2 b) {
    asm("fma.rn.f32x2 %0, %1, %2, %0;"
        : "+l"(*reinterpret_cast<unsigned long long*>(&d))
        : "l"(*reinterpret_cast<const unsigned long long*>(&a)),
          "l"(*reinterpret_cast<const unsigned long long*>(&b)));
}

__device__ __forceinline__ float4 LD4(const float* p) { return *reinterpret_cast<const float4*>(p); }
__device__ __forceinline__ void  ST4(float* p, float4 v) { *reinterpret_cast<float4*>(p) = v; }
__device__ __forceinline__ float sigm(float x) { return 1.0f / (1.0f + expf(-x)); }

// GEMM core: thread computes 2 columns {jj, jj+128} x 8 rows [aoff, aoff+8).
//   acc[0..3]: col jj     (row pairs)
//   acc[4..7]: col jj+128 (same rows)
// inA: smem [K][ST], pre-offset by aoff; Wc: global packed float2, row stride RW.
// Shallow weight-only prefetch (chunk of 8 k); activation LDS.128 inline.
template<int K, int RW>
__device__ __forceinline__ void gemm2(const float* __restrict__ inA,
                                      const float2* __restrict__ Wc,
                                      float2 acc[8]) {
    const float2* wp = Wc;
    float2 w[8];
#pragma unroll
    for (int i = 0; i < 8; i++) w[i] = wp[i * RW];
#pragma unroll 1
    for (int k0 = 0; k0 < K; k0 += 8) {
        const float2* wnp = (k0 + 8 < K) ? (wp + 8 * RW) : Wc;  // dummy on last
        float2 wn[8];
#pragma unroll
        for (int i = 0; i < 8; i++) wn[i] = wnp[i * RW];
#pragma unroll
        for (int i = 0; i < 8; i++) {
            const float* ap = inA + (k0 + i) * ST;
            float4 a0 = LD4(ap), a1 = LD4(ap + 4);
            float2 wx = make_float2(w[i].x, w[i].x);
            float2 wy = make_float2(w[i].y, w[i].y);
            ffma2(acc[0], make_float2(a0.x, a0.y), wx);
            ffma2(acc[1], make_float2(a0.z, a0.w), wx);
            ffma2(acc[2], make_float2(a1.x, a1.y), wx);
            ffma2(acc[3], make_float2(a1.z, a1.w), wx);
            ffma2(acc[4], make_float2(a0.x, a0.y), wy);
            ffma2(acc[5], make_float2(a0.z, a0.w), wy);
            ffma2(acc[6], make_float2(a1.x, a1.y), wy);
            ffma2(acc[7], make_float2(a1.z, a1.w), wy);
        }
#pragma unroll
        for (int i = 0; i < 8; i++) w[i] = wn[i];
        wp += 8 * RW;
    }
}

// one evaluation of f: out = tanh(in @ W1^T + b1) @ W2^T + b2
// Tb MAY ALIAS in (As): a __syncthreads separates gemm1 reads from Tb writes.
// ACCH: accumulate h += dt * (11/84) * f(in).
template<bool ACCH>
__device__ __forceinline__ void feval(const float* __restrict__ inT,
                                      float* __restrict__ outT,
                                      float* __restrict__ Tb,
                                      const float* __restrict__ dt8,
                                      int jj, int aoff,
                                      float b1a, float b1b, float b2a, float b2b) {
    float2 acc[8];
#pragma unroll
    for (int i = 0; i < 8; i++) acc[i] = make_float2(0.f, 0.f);
    gemm2<HDIM, 128>(inT + aoff, g_W1p + jj, acc);
    __syncthreads();   // all gemm1 reads of inT done before Tb (==inT) writes
    {
        float4 v0 = make_float4(tanhf(acc[0].x + b1a), tanhf(acc[0].y + b1a),
                                tanhf(acc[1].x + b1a), tanhf(acc[1].y + b1a));
        float4 v1 = make_float4(tanhf(acc[2].x + b1a), tanhf(acc[2].y + b1a),
                                tanhf(acc[3].x + b1a), tanhf(acc[3].y + b1a));
        float4 v2 = make_float4(tanhf(acc[4].x + b1b), tanhf(acc[4].y + b1b),
                                tanhf(acc[5].x + b1b), tanhf(acc[5].y + b1b));
        float4 v3 = make_float4(tanhf(acc[6].x + b1b), tanhf(acc[6].y + b1b),
                                tanhf(acc[7].x + b1b), tanhf(acc[7].y + b1b));
        ST4(Tb + jj * ST + aoff, v0);
        ST4(Tb + jj * ST + aoff + 4, v1);
        ST4(Tb + (jj + 128) * ST + aoff, v2);
        ST4(Tb + (jj + 128) * ST + aoff + 4, v3);
    }
    __syncthreads();
#pragma unroll
    for (int i = 0; i < 8; i++) acc[i] = make_float2(0.f, 0.f);
    gemm2<HDIM, 128>(Tb + aoff, g_W2p + jj, acc);
    {
        float* ow0 = outT + jj * ST + aoff;
        float* ow1 = outT + (jj + 128) * ST + aoff;
        if (ACCH) {
            const float C6 = (float)(11.0 / 84.0);
            float4 h0v = LD4(ow0), h1v = LD4(ow0 + 4);
            float4 h2v = LD4(ow1), h3v = LD4(ow1 + 4);
            h0v.x += dt8[0] * C6 * (acc[0].x + b2a);
            h0v.y += dt8[1] * C6 * (acc[0].y + b2a);
            h0v.z += dt8[2] * C6 * (acc[1].x + b2a);
            h0v.w += dt8[3] * C6 * (acc[1].y + b2a);
            h1v.x += dt8[4] * C6 * (acc[2].x + b2a);
            h1v.y += dt8[5] * C6 * (acc[2].y + b2a);
            h1v.z += dt8[6] * C6 * (acc[3].x + b2a);
            h1v.w += dt8[7] * C6 * (acc[3].y + b2a);
            h2v.x += dt8[0] * C6 * (acc[4].x + b2b);
            h2v.y += dt8[1] * C6 * (acc[4].y + b2b);
            h2v.z += dt8[2] * C6 * (acc[5].x + b2b);
            h2v.w += dt8[3] * C6 * (acc[5].y + b2b);
            h3v.x += dt8[4] * C6 * (acc[6].x + b2b);
            h3v.y += dt8[5] * C6 * (acc[6].y + b2b);
            h3v.z += dt8[6] * C6 * (acc[7].x + b2b);
            h3v.w += dt8[7] * C6 * (acc[7].y + b2b);
            ST4(ow0, h0v); ST4(ow0 + 4, h1v);
            ST4(ow1, h2v); ST4(ow1 + 4, h3v);
        } else {
            ST4(ow0,     make_float4(acc[0].x + b2a, acc[0].y + b2a, acc[1].x + b2a, acc[1].y + b2a));
            ST4(ow0 + 4, make_float4(acc[2].x + b2a, acc[2].y + b2a, acc[3].x + b2a, acc[3].y + b2a));
            ST4(ow1,     make_float4(acc[4].x + b2b, acc[4].y + b2b, acc[5].x + b2b, acc[5].y + b2b));
            ST4(ow1 + 4, make_float4(acc[6].x + b2b, acc[6].y + b2b, acc[7].x + b2b, acc[7].y + b2b));
        }
    }
    __syncthreads();
}

#define BUF (HDIM * ST)  // 4096 floats per state buffer
#define SMEM_FLOATS (7 * BUF + MT)
#define SMEM_BYTES  (SMEM_FLOATS * 4)   // 114752 B -> 2 CTAs/SM

__global__ void __launch_bounds__(TPB, 2)
ode_lstm_kernel(const float* __restrict__ x,  const float* __restrict__ h0,
                const float* __restrict__ c0, const float* __restrict__ ts,
                const float* __restrict__ b_ih, const float* __restrict__ b_hh,
                const float* __restrict__ b1,   const float* __restrict__ b2,
                float* __restrict__ out) {
    extern __shared__ float s[];
    float* Hs = s;
    float* K1 = s + 1 * BUF;
    float* K2 = s + 2 * BUF;
    float* K3 = s + 3 * BUF;
    float* K4 = s + 4 * BUF;
    float* K5 = s + 5 * BUF;
    float* AT = s + 6 * BUF;          // As / Tb shared; XT overlay in LSTM phase
    float* DT = s + 7 * BUF;          // [MT]

    const int t = threadIdx.x;
    const int rowBase = blockIdx.x * MT;

    // GEMM mapping: 2 columns x 8 rows per thread
    const int jj   = t & 127;
    const int aoff = (t >> 7) * 8;    // 0 or 8

    // Elementwise mapping: thread t = column t, all 16 rows
    const int b = t * ST;

    // ---- loads (coalesced across t) ----
#pragma unroll
    for (int m = 0; m < MT; m++)
        Hs[b + m] = h0[(size_t)(rowBase + m) * HDIM + t];
    if (t < MT) DT[t] = ts[rowBase + t] * (1.0f / NSTEPS);
    const float b1a = b1[jj], b1b = b1[jj + 128];
    const float b2a = b2[jj], b2b = b2[jj + 128];
    __syncthreads();

    float dtm[MT];
#pragma unroll
    for (int m = 0; m < MT; m++) dtm[m] = DT[m];
    float dt8[8];
#pragma unroll
    for (int i = 0; i < 8; i++) dt8[i] = DT[aoff + i];

    // dopri5 tableau
    const float A21 = 0.2f;
    const float A31 = 0.075f, A32 = 0.225f;
    const float A41 = (float)(44.0 / 45.0), A42 = (float)(-56.0 / 15.0), A43 = (float)(32.0 / 9.0);
    const float A51 = (float)(19372.0 / 6561.0), A52 = (float)(-25360.0 / 2187.0),
                A53 = (float)(64448.0 / 6561.0), A54 = (float)(-212.0 / 729.0);
    const float A61 = (float)(9017.0 / 3168.0), A62 = (float)(-355.0 / 33.0),
                A63 = (float)(46732.0 / 5247.0), A64 = (float)(49.0 / 176.0),
                A65 = (float)(-5103.0 / 18656.0);
    const float C1 = (float)(35.0 / 384.0), C3 = (float)(500.0 / 1113.0),
                C4 = (float)(125.0 / 192.0), C5 = (float)(-2187.0 / 6784.0);

    // ================= ODE: 8 RK45 steps =================
#pragma unroll 1
    for (int step = 0; step < NSTEPS; step++) {
        // k1 = f(h)   (Tb==AT, free here)
        feval<false>(Hs, K1, AT, dt8, jj, aoff, b1a, b1b, b2a, b2b);

        // A = h + dt*a21*k1
#pragma unroll
        for (int q = 0; q < 4; q++) {
            float h4[4], k1v[4], av[4];
            *(float4*)h4  = LD4(Hs + b + 4 * q);
            *(float4*)k1v = LD4(K1 + b + 4 * q);
#pragma unroll
            for (int c = 0; c < 4; c++)
                av[c] = h4[c] + dtm[4 * q + c] * (A21 * k1v[c]);
            ST4(AT + b + 4 * q, *(float4*)av);
        }
        __syncthreads();
        feval<false>(AT, K2, AT, dt8, jj, aoff, b1a, b1b, b2a, b2b);

        // A = h + dt*(a31 k1 + a32 k2)
#pragma unroll
        for (int q = 0; q < 4; q++) {
            float h4[4], k1v[4], k2v[4], av[4];
            *(float4*)h4  = LD4(Hs + b + 4 * q);
            *(float4*)k1v = LD4(K1 + b + 4 * q);
            *(float4*)k2v = LD4(K2 + b + 4 * q);
#pragma unroll
            for (int c = 0; c < 4; c++)
                av[c] = h4[c] + dtm[4 * q + c] * (A31 * k1v[c] + A32 * k2v[c]);
            ST4(AT + b + 4 * q, *(float4*)av);
        }
        __syncthreads();
        feval<false>(AT, K3, AT, dt8, jj, aoff, b1a, b1b, b2a, b2b);

        // A = h + dt*(a41 k1 + a42 k2 + a43 k3)
#pragma unroll
        for (int q = 0; q < 4; q++) {
            float h4[4], k1v[4], k2v[4], k3v[4], av[4];
            *(float4*)h4  = LD4(Hs + b + 4 * q);
            *(float4*)k1v = LD4(K1 + b + 4 * q);
            *(float4*)k2v = LD4(K2 + b + 4 * q);
            *(float4*)k3v = LD4(K3 + b + 4 * q);
#pragma unroll
            for (int c = 0; c < 4; c++)
                av[c] = h4[c] + dtm[4 * q + c] *
                        (A41 * k1v[c] + A42 * k2v[c] + A43 * k3v[c]);
            ST4(AT + b + 4 * q, *(float4*)av);
        }
        __syncthreads();
        feval<false>(AT, K4, AT, dt8, jj, aoff, b1a, b1b, b2a, b2b);

        // A = h + dt*(a51 k1 + a52 k2 + a53 k3 + a54 k4)
#pragma unroll
        for (int q = 0; q < 4; q++) {
            float h4[4], k1v[4], k2v[4], k3v[4], k4v[4], av[4];
            *(float4*)h4  = LD4(Hs + b + 4 * q);
            *(float4*)k1v = LD4(K1 + b + 4 * q);
            *(float4*)k2v = LD4(K2 + b + 4 * q);
            *(float4*)k3v = LD4(K3 + b + 4 * q);
            *(float4*)k4v = LD4(K4 + b + 4 * q);
#pragma unroll
            for (int c = 0; c < 4; c++)
                av[c] = h4[c] + dtm[4 * q + c] *
                        (A51 * k1v[c] + A52 * k2v[c] + A53 * k3v[c] + A54 * k4v[c]);
            ST4(AT + b + 4 * q, *(float4*)av);
        }
        __syncthreads();
        feval<false>(AT, K5, AT, dt8, jj, aoff, b1a, b1b, b2a, b2b);

        // A = h + dt*(a61..a65 · k);  h = h + dt*(c1 k1 + c3 k3 + c4 k4 + c5 k5)
#pragma unroll
        for (int q = 0; q < 4; q++) {
            float h4[4], k1v[4], k2v[4], k3v[4], k4v[4], k5v[4], av[4], hn[4];
            *(float4*)h4  = LD4(Hs + b + 4 * q);
            *(float4*)k1v = LD4(K1 + b + 4 * q);
            *(float4*)k2v = LD4(K2 + b + 4 * q);
            *(float4*)k3v = LD4(K3 + b + 4 * q);
            *(float4*)k4v = LD4(K4 + b + 4 * q);
            *(float4*)k5v = LD4(K5 + b + 4 * q);
#pragma unroll
            for (int c = 0; c < 4; c++) {
                float d = dtm[4 * q + c];
                av[c] = h4[c] + d * (A61 * k1v[c] + A62 * k2v[c] + A63 * k3v[c] +
                                     A64 * k4v[c] + A65 * k5v[c]);
                hn[c] = h4[c] + d * (C1 * k1v[c] + C3 * k3v[c] + C4 * k4v[c] + C5 * k5v[c]);
            }
            ST4(AT + b + 4 * q, *(float4*)av);
            ST4(Hs + b + 4 * q, *(float4*)hn);
        }
        __syncthreads();
        // k6 = f(A); h += dt*(11/84)*k6  (fused epilogue)
        feval<true>(AT, Hs, AT, dt8, jj, aoff, b1a, b1b, b2a, b2b);
    }

    // ================= two weight-shared LSTM cells =================
    float* Cs = K5;  // alias free buffers
    float* G0 = K1; float* G1 = K2; float* G2 = K3; float* G3 = K4;
    float* XT = AT;  // [128][ST] overlay — AT free now; reload x from global

#pragma unroll
    for (int m = 0; m < MT; m++)
        Cs[b + m] = c0[(size_t)(rowBase + m) * HDIM + t];
    if (t < IDIM) {
#pragma unroll
        for (int m = 0; m < MT; m++)
            XT[t * ST + m] = x[(size_t)(rowBase + m) * IDIM + t];
    }
    __syncthreads();

#pragma unroll 1
    for (int cell = 0; cell < 2; cell++) {
#pragma unroll 1
        for (int q = 0; q < 4; q++) {
            float2 acc[8];
#pragma unroll
            for (int i = 0; i < 8; i++) acc[i] = make_float2(0.f, 0.f);
            gemm2<IDIM, 512>(XT + aoff, g_Wihp + q * 128 + jj, acc);
            gemm2<HDIM, 512>(Hs + aoff, g_Whhp + q * 128 + jj, acc);
            const float bza = b_ih[q * 256 + jj]       + b_hh[q * 256 + jj];
            const float bzb = b_ih[q * 256 + jj + 128] + b_hh[q * 256 + jj + 128];
            float* Gq = (q == 0) ? G0 : (q == 1) ? G1 : (q == 2) ? G2 : G3;
            float va[8], vb[8];
#pragma unroll
            for (int p = 0; p < 4; p++) {
                va[2 * p] = acc[p].x + bza;     va[2 * p + 1] = acc[p].y + bza;
                vb[2 * p] = acc[4 + p].x + bzb; vb[2 * p + 1] = acc[4 + p].y + bzb;
            }
            float4 o0, o1, o2, o3;
            if (q == 2) {
                o0 = make_float4(tanhf(va[0]), tanhf(va[1]), tanhf(va[2]), tanhf(va[3]));
                o1 = make_float4(tanhf(va[4]), tanhf(va[5]), tanhf(va[6]), tanhf(va[7]));
                o2 = make_float4(tanhf(vb[0]), tanhf(vb[1]), tanhf(vb[2]), tanhf(vb[3]));
                o3 = make_float4(tanhf(vb[4]), tanhf(vb[5]), tanhf(vb[6]), tanhf(vb[7]));
            } else {
                o0 = make_float4(sigm(va[0]), sigm(va[1]), sigm(va[2]), sigm(va[3]));
                o1 = make_float4(sigm(va[4]), sigm(va[5]), sigm(va[6]), sigm(va[7]));
                o2 = make_float4(sigm(vb[0]), sigm(vb[1]), sigm(vb[2]), sigm(vb[3]));
                o3 = make_float4(sigm(vb[4]), sigm(vb[5]), sigm(vb[6]), sigm(vb[7]));
            }
            ST4(Gq + jj * ST + aoff, o0);
            ST4(Gq + jj * ST + aoff + 4, o1);
            ST4(Gq + (jj + 128) * ST + aoff, o2);
            ST4(Gq + (jj + 128) * ST + aoff + 4, o3);
        }
        __syncthreads();
#pragma unroll
        for (int m = 0; m < MT; m++) {
            float iv = G0[b + m], fv = G1[b + m], gv = G2[b + m], ov = G3[b + m];
            float cn = fv * Cs[b + m] + iv * gv;
            Cs[b + m] = cn;
            Hs[b + m] = ov * tanhf(cn);
        }
        __syncthreads();
    }

    // ---- store h2 then c2 (coalesced) ----
    const size_t BH = (size_t)B_TOTAL * HDIM;
#pragma unroll
    for (int m = 0; m < MT; m++) {
        out[(size_t)(rowBase + m) * HDIM + t]      = Hs[b + m];
        out[BH + (size_t)(rowBase + m) * HDIM + t] = Cs[b + m];
    }
}

extern "C" void kernel_launch(void* const* d_in, const int* in_sizes, int n_in,
                              void* d_out, int out_size) {
    const float* x    = (const float*)d_in[0];
    const float* h0   = (const float*)d_in[1];
    const float* c0   = (const float*)d_in[2];
    const float* ts   = (const float*)d_in[3];
    const float* W_ih = (const float*)d_in[4];
    const float* W_hh = (const float*)d_in[5];
    const float* b_ih = (const float*)d_in[6];
    const float* b_hh = (const float*)d_in[7];
    const float* W1   = (const float*)d_in[8];
    const float* b1   = (const float*)d_in[9];
    const float* W2   = (const float*)d_in[10];
    const float* b2   = (const float*)d_in[11];
    float* out = (float*)d_out;

    cudaFuncSetAttribute(ode_lstm_kernel,
                         cudaFuncAttributeMaxDynamicSharedMemorySize, SMEM_BYTES);

    prep_kernel<<<512, 256>>>(W1, W2, W_ih, W_hh);
    ode_lstm_kernel<<<B_TOTAL / MT, TPB, SMEM_BYTES>>>(
        x, h0, c0, ts, b_ih, b_hh, b1, b2, out);
}

// round 9
// speedup vs baseline: 1.5709x; 1.0002x over previous
#include <cuda_runtime.h>
#include <math.h>
#include <stdint.h>

// ----------------------------------------------------------------------------
// ODELSTMCell: B=16384, I=128, H=256
// R7: 256 threads/CTA, MT=16 rows, balanced GEMM tile TJ=2 x TM=8
//   (per k: 1 LDG.64 weights + 2 broadcast LDS.128 acts + 8 FFMA2
//    -> 32 wavefronts : 32 FMA-cyc per CTA per k, 1:1).
// SMEM trimmed to 112 KB (ST=16, Tb aliased onto As, XT reloaded late) so
// TWO CTAs co-reside per SM -> 16 warps/SM for latency hiding (R5's tile
// was wf-optimal but starved at 8 warps; R6 proved 16 warps reach ~49% issue).
// ----------------------------------------------------------------------------

#define B_TOTAL 16384
#define HDIM    256
#define IDIM    128
#define MT      16     // batch rows per CTA  (1024 CTAs)
#define ST      16     // smem row stride in floats (no pad; GEMM reads broadcast)
#define NSTEPS  8
#define TPB     256

// --- packed transposed weight scratch ---
// g_W1p[k*128 + jj] = ( W1[jj][k], W1[jj+128][k] )   [256][128] float2
// g_W2p same. g_Wihp/g_Whhp: [k][q*128+jj] pairs (j0=q*256+jj, j0+128).
__device__ float2 g_W1p [HDIM * 128];
__device__ float2 g_W2p [HDIM * 128];
__device__ float2 g_Wihp[IDIM * 512];
__device__ float2 g_Whhp[HDIM * 512];

__global__ void prep_kernel(const float* __restrict__ W1, const float* __restrict__ W2,
                            const float* __restrict__ Wih, const float* __restrict__ Whh) {
    int i0 = blockIdx.x * blockDim.x + threadIdx.x;
    int gs = gridDim.x * blockDim.x;
    for (int p = i0; p < HDIM * 128; p += gs) {           // p = k*128 + jj
        int k = p >> 7, jj = p & 127;
        g_W1p[p] = make_float2(W1[jj * HDIM + k], W1[(jj + 128) * HDIM + k]);
        g_W2p[p] = make_float2(W2[jj * HDIM + k], W2[(jj + 128) * HDIM + k]);
    }
    for (int p = i0; p < IDIM * 512; p += gs) {           // p = k*512 + q*128 + jj
        int k = p >> 9, r = p & 511, q = r >> 7, jj = r & 127;
        int j0 = q * 256 + jj;
        g_Wihp[p] = make_float2(Wih[j0 * IDIM + k], Wih[(j0 + 128) * IDIM + k]);
    }
    for (int p = i0; p < HDIM * 512; p += gs) {
        int k = p >> 9, r = p & 511, q = r >> 7, jj = r & 127;
        int j0 = q * 256 + jj;
        g_Whhp[p] = make_float2(Whh[j0 * HDIM + k], Whh[(j0 + 128) * HDIM + k]);
    }
}

// --- packed fp32x2 FMA (sm_100+): d = a*b + d ---
__device__ __forceinline__ void ffma2(float2& d, float2 a, float2 b) {
    asm("fma.rn.f32x2 %0, %1, %2, %0;"
        : "+l"(*reinterpret_cast<unsigned long long*>(&d))
        : "l"(*reinterpret_cast<const unsigned long long*>(&a)),
          "l"(*reinterpret_cast<const unsigned long long*>(&b)));
}

__device__ __forceinline__ float4 LD4(const float* p) { return *reinterpret_cast<const float4*>(p); }
__device__ __forceinline__ void  ST4(float* p, float4 v) { *reinterpret_cast<float4*>(p) = v; }
__device__ __forceinline__ float sigm(float x) { return 1.0f / (1.0f + expf(-x)); }

// GEMM core: thread computes 2 columns {jj, jj+128} x 8 rows [aoff, aoff+8).
//   acc[0..3]: col jj     (row pairs)
//   acc[4..7]: col jj+128 (same rows)
// inA: smem [K][ST], pre-offset by aoff; Wc: global packed float2, row stride RW.
// Shallow weight-only prefetch (chunk of 8 k); activation LDS.128 inline.
template<int K, int RW>
__device__ __forceinline__ void gemm2(const float* __restrict__ inA,
                                      const float2* __restrict__ Wc,
                                      float2 acc[8]) {
    const float2* wp = Wc;
    float2 w[8];
#pragma unroll
    for (int i = 0; i < 8; i++) w[i] = wp[i * RW];
#pragma unroll 1
    for (int k0 = 0; k0 < K; k0 += 8) {
        const float2* wnp = (k0 + 8 < K) ? (wp + 8 * RW) : Wc;  // dummy on last
        float2 wn[8];
#pragma unroll
        for (int i = 0; i < 8; i++) wn[i] = wnp[i * RW];
#pragma unroll
        for (int i = 0; i < 8; i++) {
            const float* ap = inA + (k0 + i) * ST;
            float4 a0 = LD4(ap), a1 = LD4(ap + 4);
            float2 wx = make_float2(w[i].x, w[i].x);
            float2 wy = make_float2(w[i].y, w[i].y);
            ffma2(acc[0], make_float2(a0.x, a0.y), wx);
            ffma2(acc[1], make_float2(a0.z, a0.w), wx);
            ffma2(acc[2], make_float2(a1.x, a1.y), wx);
            ffma2(acc[3], make_float2(a1.z, a1.w), wx);
            ffma2(acc[4], make_float2(a0.x, a0.y), wy);
            ffma2(acc[5], make_float2(a0.z, a0.w), wy);
            ffma2(acc[6], make_float2(a1.x, a1.y), wy);
            ffma2(acc[7], make_float2(a1.z, a1.w), wy);
        }
#pragma unroll
        for (int i = 0; i < 8; i++) w[i] = wn[i];
        wp += 8 * RW;
    }
}

// one evaluation of f: out = tanh(in @ W1^T + b1) @ W2^T + b2
// Tb MAY ALIAS in (As): a __syncthreads separates gemm1 reads from Tb writes.
// ACCH: accumulate h += dt * (11/84) * f(in).
template<bool ACCH>
__device__ __forceinline__ void feval(const float* __restrict__ inT,
                                      float* __restrict__ outT,
                                      float* __restrict__ Tb,
                                      const float* __restrict__ dt8,
                                      int jj, int aoff,
                                      float b1a, float b1b, float b2a, float b2b) {
    float2 acc[8];
#pragma unroll
    for (int i = 0; i < 8; i++) acc[i] = make_float2(0.f, 0.f);
    gemm2<HDIM, 128>(inT + aoff, g_W1p + jj, acc);
    __syncthreads();   // all gemm1 reads of inT done before Tb (==inT) writes
    {
        float4 v0 = make_float4(tanhf(acc[0].x + b1a), tanhf(acc[0].y + b1a),
                                tanhf(acc[1].x + b1a), tanhf(acc[1].y + b1a));
        float4 v1 = make_float4(tanhf(acc[2].x + b1a), tanhf(acc[2].y + b1a),
                                tanhf(acc[3].x + b1a), tanhf(acc[3].y + b1a));
        float4 v2 = make_float4(tanhf(acc[4].x + b1b), tanhf(acc[4].y + b1b),
                                tanhf(acc[5].x + b1b), tanhf(acc[5].y + b1b));
        float4 v3 = make_float4(tanhf(acc[6].x + b1b), tanhf(acc[6].y + b1b),
                                tanhf(acc[7].x + b1b), tanhf(acc[7].y + b1b));
        ST4(Tb + jj * ST + aoff, v0);
        ST4(Tb + jj * ST + aoff + 4, v1);
        ST4(Tb + (jj + 128) * ST + aoff, v2);
        ST4(Tb + (jj + 128) * ST + aoff + 4, v3);
    }
    __syncthreads();
#pragma unroll
    for (int i = 0; i < 8; i++) acc[i] = make_float2(0.f, 0.f);
    gemm2<HDIM, 128>(Tb + aoff, g_W2p + jj, acc);
    {
        float* ow0 = outT + jj * ST + aoff;
        float* ow1 = outT + (jj + 128) * ST + aoff;
        if (ACCH) {
            const float C6 = (float)(11.0 / 84.0);
            float4 h0v = LD4(ow0), h1v = LD4(ow0 + 4);
            float4 h2v = LD4(ow1), h3v = LD4(ow1 + 4);
            h0v.x += dt8[0] * C6 * (acc[0].x + b2a);
            h0v.y += dt8[1] * C6 * (acc[0].y + b2a);
            h0v.z += dt8[2] * C6 * (acc[1].x + b2a);
            h0v.w += dt8[3] * C6 * (acc[1].y + b2a);
            h1v.x += dt8[4] * C6 * (acc[2].x + b2a);
            h1v.y += dt8[5] * C6 * (acc[2].y + b2a);
            h1v.z += dt8[6] * C6 * (acc[3].x + b2a);
            h1v.w += dt8[7] * C6 * (acc[3].y + b2a);
            h2v.x += dt8[0] * C6 * (acc[4].x + b2b);
            h2v.y += dt8[1] * C6 * (acc[4].y + b2b);
            h2v.z += dt8[2] * C6 * (acc[5].x + b2b);
            h2v.w += dt8[3] * C6 * (acc[5].y + b2b);
            h3v.x += dt8[4] * C6 * (acc[6].x + b2b);
            h3v.y += dt8[5] * C6 * (acc[6].y + b2b);
            h3v.z += dt8[6] * C6 * (acc[7].x + b2b);
            h3v.w += dt8[7] * C6 * (acc[7].y + b2b);
            ST4(ow0, h0v); ST4(ow0 + 4, h1v);
            ST4(ow1, h2v); ST4(ow1 + 4, h3v);
        } else {
            ST4(ow0,     make_float4(acc[0].x + b2a, acc[0].y + b2a, acc[1].x + b2a, acc[1].y + b2a));
            ST4(ow0 + 4, make_float4(acc[2].x + b2a, acc[2].y + b2a, acc[3].x + b2a, acc[3].y + b2a));
            ST4(ow1,     make_float4(acc[4].x + b2b, acc[4].y + b2b, acc[5].x + b2b, acc[5].y + b2b));
            ST4(ow1 + 4, make_float4(acc[6].x + b2b, acc[6].y + b2b, acc[7].x + b2b, acc[7].y + b2b));
        }
    }
    __syncthreads();
}

#define BUF (HDIM * ST)  // 4096 floats per state buffer
#define SMEM_FLOATS (7 * BUF + MT)
#define SMEM_BYTES  (SMEM_FLOATS * 4)   // 114752 B -> 2 CTAs/SM

__global__ void __launch_bounds__(TPB, 2)
ode_lstm_kernel(const float* __restrict__ x,  const float* __restrict__ h0,
                const float* __restrict__ c0, const float* __restrict__ ts,
                const float* __restrict__ b_ih, const float* __restrict__ b_hh,
                const float* __restrict__ b1,   const float* __restrict__ b2,
                float* __restrict__ out) {
    extern __shared__ float s[];
    float* Hs = s;
    float* K1 = s + 1 * BUF;
    float* K2 = s + 2 * BUF;
    float* K3 = s + 3 * BUF;
    float* K4 = s + 4 * BUF;
    float* K5 = s + 5 * BUF;
    float* AT = s + 6 * BUF;          // As / Tb shared; XT overlay in LSTM phase
    float* DT = s + 7 * BUF;          // [MT]

    const int t = threadIdx.x;
    const int rowBase = blockIdx.x * MT;

    // GEMM mapping: 2 columns x 8 rows per thread
    const int jj   = t & 127;
    const int aoff = (t >> 7) * 8;    // 0 or 8

    // Elementwise mapping: thread t = column t, all 16 rows
    const int b = t * ST;

    // ---- loads (coalesced across t) ----
#pragma unroll
    for (int m = 0; m < MT; m++)
        Hs[b + m] = h0[(size_t)(rowBase + m) * HDIM + t];
    if (t < MT) DT[t] = ts[rowBase + t] * (1.0f / NSTEPS);
    const float b1a = b1[jj], b1b = b1[jj + 128];
    const float b2a = b2[jj], b2b = b2[jj + 128];
    __syncthreads();

    float dtm[MT];
#pragma unroll
    for (int m = 0; m < MT; m++) dtm[m] = DT[m];
    float dt8[8];
#pragma unroll
    for (int i = 0; i < 8; i++) dt8[i] = DT[aoff + i];

    // dopri5 tableau
    const float A21 = 0.2f;
    const float A31 = 0.075f, A32 = 0.225f;
    const float A41 = (float)(44.0 / 45.0), A42 = (float)(-56.0 / 15.0), A43 = (float)(32.0 / 9.0);
    const float A51 = (float)(19372.0 / 6561.0), A52 = (float)(-25360.0 / 2187.0),
                A53 = (float)(64448.0 / 6561.0), A54 = (float)(-212.0 / 729.0);
    const float A61 = (float)(9017.0 / 3168.0), A62 = (float)(-355.0 / 33.0),
                A63 = (float)(46732.0 / 5247.0), A64 = (float)(49.0 / 176.0),
                A65 = (float)(-5103.0 / 18656.0);
    const float C1 = (float)(35.0 / 384.0), C3 = (float)(500.0 / 1113.0),
                C4 = (float)(125.0 / 192.0), C5 = (float)(-2187.0 / 6784.0);

    // ================= ODE: 8 RK45 steps =================
#pragma unroll 1
    for (int step = 0; step < NSTEPS; step++) {
        // k1 = f(h)   (Tb==AT, free here)
        feval<false>(Hs, K1, AT, dt8, jj, aoff, b1a, b1b, b2a, b2b);

        // A = h + dt*a21*k1
#pragma unroll
        for (int q = 0; q < 4; q++) {
            float h4[4], k1v[4], av[4];
            *(float4*)h4  = LD4(Hs + b + 4 * q);
            *(float4*)k1v = LD4(K1 + b + 4 * q);
#pragma unroll
            for (int c = 0; c < 4; c++)
                av[c] = h4[c] + dtm[4 * q + c] * (A21 * k1v[c]);
            ST4(AT + b + 4 * q, *(float4*)av);
        }
        __syncthreads();
        feval<false>(AT, K2, AT, dt8, jj, aoff, b1a, b1b, b2a, b2b);

        // A = h + dt*(a31 k1 + a32 k2)
#pragma unroll
        for (int q = 0; q < 4; q++) {
            float h4[4], k1v[4], k2v[4], av[4];
            *(float4*)h4  = LD4(Hs + b + 4 * q);
            *(float4*)k1v = LD4(K1 + b + 4 * q);
            *(float4*)k2v = LD4(K2 + b + 4 * q);
#pragma unroll
            for (int c = 0; c < 4; c++)
                av[c] = h4[c] + dtm[4 * q + c] * (A31 * k1v[c] + A32 * k2v[c]);
            ST4(AT + b + 4 * q, *(float4*)av);
        }
        __syncthreads();
        feval<false>(AT, K3, AT, dt8, jj, aoff, b1a, b1b, b2a, b2b);

        // A = h + dt*(a41 k1 + a42 k2 + a43 k3)
#pragma unroll
        for (int q = 0; q < 4; q++) {
            float h4[4], k1v[4], k2v[4], k3v[4], av[4];
            *(float4*)h4  = LD4(Hs + b + 4 * q);
            *(float4*)k1v = LD4(K1 + b + 4 * q);
            *(float4*)k2v = LD4(K2 + b + 4 * q);
            *(float4*)k3v = LD4(K3 + b + 4 * q);
#pragma unroll
            for (int c = 0; c < 4; c++)
                av[c] = h4[c] + dtm[4 * q + c] *
                        (A41 * k1v[c] + A42 * k2v[c] + A43 * k3v[c]);
            ST4(AT + b + 4 * q, *(float4*)av);
        }
        __syncthreads();
        feval<false>(AT, K4, AT, dt8, jj, aoff, b1a, b1b, b2a, b2b);

        // A = h + dt*(a51 k1 + a52 k2 + a53 k3 + a54 k4)
#pragma unroll
        for (int q = 0; q < 4; q++) {
            float h4[4], k1v[4], k2v[4], k3v[4], k4v[4], av[4];
            *(float4*)h4  = LD4(Hs + b + 4 * q);
            *(float4*)k1v = LD4(K1 + b + 4 * q);
            *(float4*)k2v = LD4(K2 + b + 4 * q);
            *(float4*)k3v = LD4(K3 + b + 4 * q);
            *(float4*)k4v = LD4(K4 + b + 4 * q);
#pragma unroll
            for (int c = 0; c < 4; c++)
                av[c] = h4[c] + dtm[4 * q + c] *
                        (A51 * k1v[c] + A52 * k2v[c] + A53 * k3v[c] + A54 * k4v[c]);
            ST4(AT + b + 4 * q, *(float4*)av);
        }
        __syncthreads();
        feval<false>(AT, K5, AT, dt8, jj, aoff, b1a, b1b, b2a, b2b);

        // A = h + dt*(a61..a65 · k);  h = h + dt*(c1 k1 + c3 k3 + c4 k4 + c5 k5)
#pragma unroll
        for (int q = 0; q < 4; q++) {
            float h4[4], k1v[4], k2v[4], k3v[4], k4v[4], k5v[4], av[4], hn[4];
            *(float4*)h4  = LD4(Hs + b + 4 * q);
            *(float4*)k1v = LD4(K1 + b + 4 * q);
            *(float4*)k2v = LD4(K2 + b + 4 * q);
            *(float4*)k3v = LD4(K3 + b + 4 * q);
            *(float4*)k4v = LD4(K4 + b + 4 * q);
            *(float4*)k5v = LD4(K5 + b + 4 * q);
#pragma unroll
            for (int c = 0; c < 4; c++) {
                float d = dtm[4 * q + c];
                av[c] = h4[c] + d * (A61 * k1v[c] + A62 * k2v[c] + A63 * k3v[c] +
                                     A64 * k4v[c] + A65 * k5v[c]);
                hn[c] = h4[c] + d * (C1 * k1v[c] + C3 * k3v[c] + C4 * k4v[c] + C5 * k5v[c]);
            }
            ST4(AT + b + 4 * q, *(float4*)av);
            ST4(Hs + b + 4 * q, *(float4*)hn);
        }
        __syncthreads();
        // k6 = f(A); h += dt*(11/84)*k6  (fused epilogue)
        feval<true>(AT, Hs, AT, dt8, jj, aoff, b1a, b1b, b2a, b2b);
    }

    // ================= two weight-shared LSTM cells =================
    float* Cs = K5;  // alias free buffers
    float* G0 = K1; float* G1 = K2; float* G2 = K3; float* G3 = K4;
    float* XT = AT;  // [128][ST] overlay — AT free now; reload x from global

#pragma unroll
    for (int m = 0; m < MT; m++)
        Cs[b + m] = c0[(size_t)(rowBase + m) * HDIM + t];
    if (t < IDIM) {
#pragma unroll
        for (int m = 0; m < MT; m++)
            XT[t * ST + m] = x[(size_t)(rowBase + m) * IDIM + t];
    }
    __syncthreads();

#pragma unroll 1
    for (int cell = 0; cell < 2; cell++) {
#pragma unroll 1
        for (int q = 0; q < 4; q++) {
            float2 acc[8];
#pragma unroll
            for (int i = 0; i < 8; i++) acc[i] = make_float2(0.f, 0.f);
            gemm2<IDIM, 512>(XT + aoff, g_Wihp + q * 128 + jj, acc);
            gemm2<HDIM, 512>(Hs + aoff, g_Whhp + q * 128 + jj, acc);
            const float bza = b_ih[q * 256 + jj]       + b_hh[q * 256 + jj];
            const float bzb = b_ih[q * 256 + jj + 128] + b_hh[q * 256 + jj + 128];
            float* Gq = (q == 0) ? G0 : (q == 1) ? G1 : (q == 2) ? G2 : G3;
            float va[8], vb[8];
#pragma unroll
            for (int p = 0; p < 4; p++) {
                va[2 * p] = acc[p].x + bza;     va[2 * p + 1] = acc[p].y + bza;
                vb[2 * p] = acc[4 + p].x + bzb; vb[2 * p + 1] = acc[4 + p].y + bzb;
            }
            float4 o0, o1, o2, o3;
            if (q == 2) {
                o0 = make_float4(tanhf(va[0]), tanhf(va[1]), tanhf(va[2]), tanhf(va[3]));
                o1 = make_float4(tanhf(va[4]), tanhf(va[5]), tanhf(va[6]), tanhf(va[7]));
                o2 = make_float4(tanhf(vb[0]), tanhf(vb[1]), tanhf(vb[2]), tanhf(vb[3]));
                o3 = make_float4(tanhf(vb[4]), tanhf(vb[5]), tanhf(vb[6]), tanhf(vb[7]));
            } else {
                o0 = make_float4(sigm(va[0]), sigm(va[1]), sigm(va[2]), sigm(va[3]));
                o1 = make_float4(sigm(va[4]), sigm(va[5]), sigm(va[6]), sigm(va[7]));
                o2 = make_float4(sigm(vb[0]), sigm(vb[1]), sigm(vb[2]), sigm(vb[3]));
                o3 = make_float4(sigm(vb[4]), sigm(vb[5]), sigm(vb[6]), sigm(vb[7]));
            }
            ST4(Gq + jj * ST + aoff, o0);
            ST4(Gq + jj * ST + aoff + 4, o1);
            ST4(Gq + (jj + 128) * ST + aoff, o2);
            ST4(Gq + (jj + 128) * ST + aoff + 4, o3);
        }
        __syncthreads();
#pragma unroll
        for (int m = 0; m < MT; m++) {
            float iv = G0[b + m], fv = G1[b + m], gv = G2[b + m], ov = G3[b + m];
            float cn = fv * Cs[b + m] + iv * gv;
            Cs[b + m] = cn;
            Hs[b + m] = ov * tanhf(cn);
        }
        __syncthreads();
    }

    // ---- store h2 then c2 (coalesced) ----
    const size_t BH = (size_t)B_TOTAL * HDIM;
#pragma unroll
    for (int m = 0; m < MT; m++) {
        out[(size_t)(rowBase + m) * HDIM + t]      = Hs[b + m];
        out[BH + (size_t)(rowBase + m) * HDIM + t] = Cs[b + m];
    }
}

extern "C" void kernel_launch(void* const* d_in, const int* in_sizes, int n_in,
                              void* d_out, int out_size) {
    const float* x    = (const float*)d_in[0];
    const float* h0   = (const float*)d_in[1];
    const float* c0   = (const float*)d_in[2];
    const float* ts   = (const float*)d_in[3];
    const float* W_ih = (const float*)d_in[4];
    const float* W_hh = (const float*)d_in[5];
    const float* b_ih = (const float*)d_in[6];
    const float* b_hh = (const float*)d_in[7];
    const float* W1   = (const float*)d_in[8];
    const float* b1   = (const float*)d_in[9];
    const float* W2   = (const float*)d_in[10];
    const float* b2   = (const float*)d_in[11];
    float* out = (float*)d_out;

    cudaFuncSetAttribute(ode_lstm_kernel,
                         cudaFuncAttributeMaxDynamicSharedMemorySize, SMEM_BYTES);

    prep_kernel<<<512, 256>>>(W1, W2, W_ih, W_hh);
    ode_lstm_kernel<<<B_TOTAL / MT, TPB, SMEM_BYTES>>>(
        x, h0, c0, ts, b_ih, b_hh, b1, b2, out);
}

// round 10
// speedup vs baseline: 1.6080x; 1.0236x over previous
#include <cuda_runtime.h>
#include <math.h>
#include <stdint.h>

// ----------------------------------------------------------------------------
// ODELSTMCell: B=16384, I=128, H=256
// R10: MT=32 rows/CTA (512 CTAs), 256 threads, tile TJ=2 x TM=16.
// Per k per CTA: 16 wf (LDG.64 weights) + 32 wf (broadcast LDS.128 acts)
// = 48 wf vs 64 FMA-cyc -> FMA-bound (R7 was 2:1 L1-bound).
// Buffers [256 cols][32 rows] fp32 with XOR swizzle on 16B chunks:
//   phys(c,m) = c*32 + 4*((m>>2) ^ (c&7)) + (m&3)
// -> broadcast GEMM reads 1 wf, all strided ST4/LD4 conflict-free.
// Elementwise RK combines walk physical addresses (flat), coalesced;
// per-thread dt chunk index is constant: q = (t&7) ^ ((t>>3)&7).
// 7 buffers x 32KB = 229.5 KB smem, 1 CTA/SM.
// ----------------------------------------------------------------------------

#define B_TOTAL 16384
#define HDIM    256
#define IDIM    128
#define MT      32     // batch rows per CTA  (512 CTAs)
#define NB      8192   // floats per state buffer (256*32)
#define NSTEPS  8
#define TPB     256

// swizzled float offset of logical (col c, row-chunk q) [16B chunk of 4 rows]
#define SWZ(c, q) ((c) * 32 + 4 * ((q) ^ ((c) & 7)))

// --- packed transposed weight scratch ---
// g_W1p[k*128 + jj] = ( W1[jj][k], W1[jj+128][k] )   [256][128] float2
// g_W2p same. g_Wihp/g_Whhp: [k][q*128+jj] pairs (j0=q*256+jj, j0+128).
__device__ float2 g_W1p [HDIM * 128];
__device__ float2 g_W2p [HDIM * 128];
__device__ float2 g_Wihp[IDIM * 512];
__device__ float2 g_Whhp[HDIM * 512];

__global__ void prep_kernel(const float* __restrict__ W1, const float* __restrict__ W2,
                            const float* __restrict__ Wih, const float* __restrict__ Whh) {
    int i0 = blockIdx.x * blockDim.x + threadIdx.x;
    int gs = gridDim.x * blockDim.x;
    for (int p = i0; p < HDIM * 128; p += gs) {           // p = k*128 + jj
        int k = p >> 7, jj = p & 127;
        g_W1p[p] = make_float2(W1[jj * HDIM + k], W1[(jj + 128) * HDIM + k]);
        g_W2p[p] = make_float2(W2[jj * HDIM + k], W2[(jj + 128) * HDIM + k]);
    }
    for (int p = i0; p < IDIM * 512; p += gs) {           // p = k*512 + q*128 + jj
        int k = p >> 9, r = p & 511, q = r >> 7, jj = r & 127;
        int j0 = q * 256 + jj;
        g_Wihp[p] = make_float2(Wih[j0 * IDIM + k], Wih[(j0 + 128) * IDIM + k]);
    }
    for (int p = i0; p < HDIM * 512; p += gs) {
        int k = p >> 9, r = p & 511, q = r >> 7, jj = r & 127;
        int j0 = q * 256 + jj;
        g_Whhp[p] = make_float2(Whh[j0 * HDIM + k], Whh[(j0 + 128) * HDIM + k]);
    }
}

// --- packed fp32x2 FMA (sm_100+): d = a*b + d ---
__device__ __forceinline__ void ffma2(float2& d, float2 a, float2 b) {
    asm("fma.rn.f32x2 %0, %1, %2, %0;"
        : "+l"(*reinterpret_cast<unsigned long long*>(&d))
        : "l"(*reinterpret_cast<const unsigned long long*>(&a)),
          "l"(*reinterpret_cast<const unsigned long long*>(&b)));
}

__device__ __forceinline__ float4 LD4(const float* p) { return *reinterpret_cast<const float4*>(p); }
__device__ __forceinline__ void  ST4(float* p, float4 v) { *reinterpret_cast<float4*>(p) = v; }
__device__ __forceinline__ float sigm(float x) { return 1.0f / (1.0f + expf(-x)); }

// GEMM core: thread computes 2 columns {jj, jj+128} x 16 rows [4*q0, 4*q0+16).
//   acc[0..7]:  col jj      (row pairs within chunks q0..q0+3)
//   acc[8..15]: col jj+128  (same rows)
// inT: swizzled smem buffer base; Wc: global packed float2, row stride RW.
// Weight prefetch one 8-k chunk ahead; activation LDS.128 broadcast inline.
// NOTE: relies on k0 being a multiple of 8, so (k0+i)&7 == i.
template<int K, int RW>
__device__ __forceinline__ void gemm2(const float* __restrict__ inT,
                                      int q0,
                                      const float2* __restrict__ Wc,
                                      float2 acc[16]) {
    const float2* wp = Wc;
    float2 w[8];
#pragma unroll
    for (int i = 0; i < 8; i++) w[i] = wp[i * RW];
#pragma unroll 1
    for (int k0 = 0; k0 < K; k0 += 8) {
        const float2* wnp = (k0 + 8 < K) ? (wp + 8 * RW) : Wc;  // dummy on last
        float2 wn[8];
#pragma unroll
        for (int i = 0; i < 8; i++) wn[i] = wnp[i * RW];
#pragma unroll
        for (int i = 0; i < 8; i++) {
            const float* colp = inT + (k0 + i) * 32;   // col k0+i base
            float4 a0 = LD4(colp + 4 * ((q0 + 0) ^ i));
            float4 a1 = LD4(colp + 4 * ((q0 + 1) ^ i));
            float4 a2 = LD4(colp + 4 * ((q0 + 2) ^ i));
            float4 a3 = LD4(colp + 4 * ((q0 + 3) ^ i));
            float2 wx = make_float2(w[i].x, w[i].x);
            float2 wy = make_float2(w[i].y, w[i].y);
            ffma2(acc[0],  make_float2(a0.x, a0.y), wx);
            ffma2(acc[1],  make_float2(a0.z, a0.w), wx);
            ffma2(acc[2],  make_float2(a1.x, a1.y), wx);
            ffma2(acc[3],  make_float2(a1.z, a1.w), wx);
            ffma2(acc[4],  make_float2(a2.x, a2.y), wx);
            ffma2(acc[5],  make_float2(a2.z, a2.w), wx);
            ffma2(acc[6],  make_float2(a3.x, a3.y), wx);
            ffma2(acc[7],  make_float2(a3.z, a3.w), wx);
            ffma2(acc[8],  make_float2(a0.x, a0.y), wy);
            ffma2(acc[9],  make_float2(a0.z, a0.w), wy);
            ffma2(acc[10], make_float2(a1.x, a1.y), wy);
            ffma2(acc[11], make_float2(a1.z, a1.w), wy);
            ffma2(acc[12], make_float2(a2.x, a2.y), wy);
            ffma2(acc[13], make_float2(a2.z, a2.w), wy);
            ffma2(acc[14], make_float2(a3.x, a3.y), wy);
            ffma2(acc[15], make_float2(a3.z, a3.w), wy);
        }
#pragma unroll
        for (int i = 0; i < 8; i++) w[i] = wn[i];
        wp += 8 * RW;
    }
}

// one evaluation of f: out = tanh(in @ W1^T + b1) @ W2^T + b2
// Tb MAY ALIAS inT: a __syncthreads separates gemm1 reads from Tb writes.
// ACCH: accumulate h += dt * (11/84) * f(in).
template<bool ACCH>
__device__ __forceinline__ void feval(const float* __restrict__ inT,
                                      float* __restrict__ outT,
                                      float* __restrict__ Tb,
                                      const float* __restrict__ DTs,
                                      int jj, int aoff,
                                      float b1a, float b1b, float b2a, float b2b) {
    const int q0 = aoff >> 2;
    float2 acc[16];
#pragma unroll
    for (int i = 0; i < 16; i++) acc[i] = make_float2(0.f, 0.f);
    gemm2<HDIM, 128>(inT, q0, g_W1p + jj, acc);
    __syncthreads();   // all gemm1 reads of inT done before Tb (possibly ==inT) writes
#pragma unroll
    for (int j = 0; j < 4; j++) {
        float4 v0 = make_float4(tanhf(acc[2*j].x + b1a),   tanhf(acc[2*j].y + b1a),
                                tanhf(acc[2*j+1].x + b1a), tanhf(acc[2*j+1].y + b1a));
        float4 v1 = make_float4(tanhf(acc[8+2*j].x + b1b),   tanhf(acc[8+2*j].y + b1b),
                                tanhf(acc[8+2*j+1].x + b1b), tanhf(acc[8+2*j+1].y + b1b));
        ST4(Tb + SWZ(jj, q0 + j), v0);
        ST4(Tb + SWZ(jj + 128, q0 + j), v1);
    }
    __syncthreads();
#pragma unroll
    for (int i = 0; i < 16; i++) acc[i] = make_float2(0.f, 0.f);
    gemm2<HDIM, 128>(Tb, q0, g_W2p + jj, acc);
#pragma unroll
    for (int j = 0; j < 4; j++) {
        float* p0 = outT + SWZ(jj, q0 + j);
        float* p1 = outT + SWZ(jj + 128, q0 + j);
        if (ACCH) {
            const float C6 = (float)(11.0 / 84.0);
            float4 dtv = LD4(DTs + aoff + 4 * j);
            float4 h0v = LD4(p0), h1v = LD4(p1);
            h0v.x += dtv.x * C6 * (acc[2*j].x + b2a);
            h0v.y += dtv.y * C6 * (acc[2*j].y + b2a);
            h0v.z += dtv.z * C6 * (acc[2*j+1].x + b2a);
            h0v.w += dtv.w * C6 * (acc[2*j+1].y + b2a);
            h1v.x += dtv.x * C6 * (acc[8+2*j].x + b2b);
            h1v.y += dtv.y * C6 * (acc[8+2*j].y + b2b);
            h1v.z += dtv.z * C6 * (acc[8+2*j+1].x + b2b);
            h1v.w += dtv.w * C6 * (acc[8+2*j+1].y + b2b);
            ST4(p0, h0v);
            ST4(p1, h1v);
        } else {
            ST4(p0, make_float4(acc[2*j].x + b2a,   acc[2*j].y + b2a,
                                acc[2*j+1].x + b2a, acc[2*j+1].y + b2a));
            ST4(p1, make_float4(acc[8+2*j].x + b2b,   acc[8+2*j].y + b2b,
                                acc[8+2*j+1].x + b2b, acc[8+2*j+1].y + b2b));
        }
    }
    __syncthreads();
}

#define SMEM_FLOATS (7 * NB + MT)
#define SMEM_BYTES  (SMEM_FLOATS * 4)   // 229504 B -> 1 CTA/SM

__global__ void __launch_bounds__(TPB, 1)
ode_lstm_kernel(const float* __restrict__ x,  const float* __restrict__ h0,
                const float* __restrict__ c0, const float* __restrict__ ts,
                const float* __restrict__ b_ih, const float* __restrict__ b_hh,
                const float* __restrict__ b1,   const float* __restrict__ b2,
                float* __restrict__ out) {
    extern __shared__ float s[];
    float* Hs = s;
    float* K1 = s + 1 * NB;
    float* K2 = s + 2 * NB;
    float* K3 = s + 3 * NB;
    float* K4 = s + 4 * NB;
    float* K5 = s + 5 * NB;
    float* AT = s + 6 * NB;           // A-stage / tanh scratch; XT overlay later
    float* DTs = s + 7 * NB;          // [MT] per-row dt

    const int t = threadIdx.x;
    const int rowBase = blockIdx.x * MT;

    // GEMM mapping: 2 columns x 16 rows per thread
    const int jj   = t & 127;
    const int aoff = (t >> 7) * 16;   // 0 or 16

    // Flat elementwise mapping: physical float4 at 4t + 1024*i (i=0..7).
    // Logical row chunk for this thread's float4s is constant:
    const int qe = (t & 7) ^ ((t >> 3) & 7);
    const int ft = 4 * t;

    // ---- loads ----
#pragma unroll 1
    for (int m = 0; m < MT; m++)
        Hs[SWZ(t, m >> 2) + (m & 3)] = h0[(size_t)(rowBase + m) * HDIM + t];
    if (t < MT) DTs[t] = ts[rowBase + t] * (1.0f / NSTEPS);
    const float b1a = b1[jj], b1b = b1[jj + 128];
    const float b2a = b2[jj], b2b = b2[jj + 128];
    __syncthreads();

    const float4 dte4 = LD4(DTs + 4 * qe);   // dt for this thread's 4 rows (flat phases)

    // dopri5 tableau
    const float A21 = 0.2f;
    const float A31 = 0.075f, A32 = 0.225f;
    const float A41 = (float)(44.0 / 45.0), A42 = (float)(-56.0 / 15.0), A43 = (float)(32.0 / 9.0);
    const float A51 = (float)(19372.0 / 6561.0), A52 = (float)(-25360.0 / 2187.0),
                A53 = (float)(64448.0 / 6561.0), A54 = (float)(-212.0 / 729.0);
    const float A61 = (float)(9017.0 / 3168.0), A62 = (float)(-355.0 / 33.0),
                A63 = (float)(46732.0 / 5247.0), A64 = (float)(49.0 / 176.0),
                A65 = (float)(-5103.0 / 18656.0);
    const float C1 = (float)(35.0 / 384.0), C3 = (float)(500.0 / 1113.0),
                C4 = (float)(125.0 / 192.0), C5 = (float)(-2187.0 / 6784.0);

    // ================= ODE: 8 RK45 steps =================
#pragma unroll 1
    for (int step = 0; step < NSTEPS; step++) {
        // k1 = f(h)
        feval<false>(Hs, K1, AT, DTs, jj, aoff, b1a, b1b, b2a, b2b);

        // A = h + dt*a21*k1
#pragma unroll
        for (int i = 0; i < 8; i++) {
            int p = ft + 1024 * i;
            float4 h = LD4(Hs + p), k1v = LD4(K1 + p), av;
            av.x = h.x + dte4.x * (A21 * k1v.x);
            av.y = h.y + dte4.y * (A21 * k1v.y);
            av.z = h.z + dte4.z * (A21 * k1v.z);
            av.w = h.w + dte4.w * (A21 * k1v.w);
            ST4(AT + p, av);
        }
        __syncthreads();
        feval<false>(AT, K2, AT, DTs, jj, aoff, b1a, b1b, b2a, b2b);

        // A = h + dt*(a31 k1 + a32 k2)
#pragma unroll
        for (int i = 0; i < 8; i++) {
            int p = ft + 1024 * i;
            float4 h = LD4(Hs + p), k1v = LD4(K1 + p), k2v = LD4(K2 + p), av;
            av.x = h.x + dte4.x * (A31 * k1v.x + A32 * k2v.x);
            av.y = h.y + dte4.y * (A31 * k1v.y + A32 * k2v.y);
            av.z = h.z + dte4.z * (A31 * k1v.z + A32 * k2v.z);
            av.w = h.w + dte4.w * (A31 * k1v.w + A32 * k2v.w);
            ST4(AT + p, av);
        }
        __syncthreads();
        feval<false>(AT, K3, AT, DTs, jj, aoff, b1a, b1b, b2a, b2b);

        // A = h + dt*(a41 k1 + a42 k2 + a43 k3)
#pragma unroll
        for (int i = 0; i < 8; i++) {
            int p = ft + 1024 * i;
            float4 h = LD4(Hs + p), k1v = LD4(K1 + p), k2v = LD4(K2 + p), k3v = LD4(K3 + p), av;
            av.x = h.x + dte4.x * (A41 * k1v.x + A42 * k2v.x + A43 * k3v.x);
            av.y = h.y + dte4.y * (A41 * k1v.y + A42 * k2v.y + A43 * k3v.y);
            av.z = h.z + dte4.z * (A41 * k1v.z + A42 * k2v.z + A43 * k3v.z);
            av.w = h.w + dte4.w * (A41 * k1v.w + A42 * k2v.w + A43 * k3v.w);
            ST4(AT + p, av);
        }
        __syncthreads();
        feval<false>(AT, K4, AT, DTs, jj, aoff, b1a, b1b, b2a, b2b);

        // A = h + dt*(a51 k1 + a52 k2 + a53 k3 + a54 k4)
#pragma unroll
        for (int i = 0; i < 8; i++) {
            int p = ft + 1024 * i;
            float4 h = LD4(Hs + p), k1v = LD4(K1 + p), k2v = LD4(K2 + p),
                   k3v = LD4(K3 + p), k4v = LD4(K4 + p), av;
            av.x = h.x + dte4.x * (A51 * k1v.x + A52 * k2v.x + A53 * k3v.x + A54 * k4v.x);
            av.y = h.y + dte4.y * (A51 * k1v.y + A52 * k2v.y + A53 * k3v.y + A54 * k4v.y);
            av.z = h.z + dte4.z * (A51 * k1v.z + A52 * k2v.z + A53 * k3v.z + A54 * k4v.z);
            av.w = h.w + dte4.w * (A51 * k1v.w + A52 * k2v.w + A53 * k3v.w + A54 * k4v.w);
            ST4(AT + p, av);
        }
        __syncthreads();
        feval<false>(AT, K5, AT, DTs, jj, aoff, b1a, b1b, b2a, b2b);

        // A = h + dt*(a61..a65 · k);  h = h + dt*(c1 k1 + c3 k3 + c4 k4 + c5 k5)
#pragma unroll
        for (int i = 0; i < 8; i++) {
            int p = ft + 1024 * i;
            float4 h = LD4(Hs + p), k1v = LD4(K1 + p), k2v = LD4(K2 + p),
                   k3v = LD4(K3 + p), k4v = LD4(K4 + p), k5v = LD4(K5 + p), av, hn;
            av.x = h.x + dte4.x * (A61 * k1v.x + A62 * k2v.x + A63 * k3v.x + A64 * k4v.x + A65 * k5v.x);
            av.y = h.y + dte4.y * (A61 * k1v.y + A62 * k2v.y + A63 * k3v.y + A64 * k4v.y + A65 * k5v.y);
            av.z = h.z + dte4.z * (A61 * k1v.z + A62 * k2v.z + A63 * k3v.z + A64 * k4v.z + A65 * k5v.z);
            av.w = h.w + dte4.w * (A61 * k1v.w + A62 * k2v.w + A63 * k3v.w + A64 * k4v.w + A65 * k5v.w);
            hn.x = h.x + dte4.x * (C1 * k1v.x + C3 * k3v.x + C4 * k4v.x + C5 * k5v.x);
            hn.y = h.y + dte4.y * (C1 * k1v.y + C3 * k3v.y + C4 * k4v.y + C5 * k5v.y);
            hn.z = h.z + dte4.z * (C1 * k1v.z + C3 * k3v.z + C4 * k4v.z + C5 * k5v.z);
            hn.w = h.w + dte4.w * (C1 * k1v.w + C3 * k3v.w + C4 * k4v.w + C5 * k5v.w);
            ST4(AT + p, av);
            ST4(Hs + p, hn);
        }
        __syncthreads();
        // k6 = f(A); h += dt*(11/84)*k6  (fused epilogue)
        feval<true>(AT, Hs, AT, DTs, jj, aoff, b1a, b1b, b2a, b2b);
    }

    // ================= two weight-shared LSTM cells =================
    float* Cs = K5;  // alias free buffers
    float* G0 = K1; float* G1 = K2; float* G2 = K3; float* G3 = K4;
    float* XT = AT;  // [128][32] swizzled overlay — AT free now

#pragma unroll 1
    for (int m = 0; m < MT; m++)
        Cs[SWZ(t, m >> 2) + (m & 3)] = c0[(size_t)(rowBase + m) * HDIM + t];
    {
        int cx = t & 127, m0 = (t >> 7) * 16;
#pragma unroll 1
        for (int mm = 0; mm < 16; mm++) {
            int m = m0 + mm;
            XT[SWZ(cx, m >> 2) + (m & 3)] = x[(size_t)(rowBase + m) * IDIM + cx];
        }
    }
    __syncthreads();

    const int q0 = aoff >> 2;
#pragma unroll 1
    for (int cell = 0; cell < 2; cell++) {
#pragma unroll 1
        for (int qg = 0; qg < 4; qg++) {
            float2 acc[16];
#pragma unroll
            for (int i = 0; i < 16; i++) acc[i] = make_float2(0.f, 0.f);
            gemm2<IDIM, 512>(XT, q0, g_Wihp + qg * 128 + jj, acc);
            gemm2<HDIM, 512>(Hs, q0, g_Whhp + qg * 128 + jj, acc);
            const float bza = b_ih[qg * 256 + jj]       + b_hh[qg * 256 + jj];
            const float bzb = b_ih[qg * 256 + jj + 128] + b_hh[qg * 256 + jj + 128];
            float* Gq = (qg == 0) ? G0 : (qg == 1) ? G1 : (qg == 2) ? G2 : G3;
#pragma unroll
            for (int j = 0; j < 4; j++) {
                float va0 = acc[2*j].x + bza,   va1 = acc[2*j].y + bza;
                float va2 = acc[2*j+1].x + bza, va3 = acc[2*j+1].y + bza;
                float vb0 = acc[8+2*j].x + bzb,   vb1 = acc[8+2*j].y + bzb;
                float vb2 = acc[8+2*j+1].x + bzb, vb3 = acc[8+2*j+1].y + bzb;
                float4 o0, o1;
                if (qg == 2) {
                    o0 = make_float4(tanhf(va0), tanhf(va1), tanhf(va2), tanhf(va3));
                    o1 = make_float4(tanhf(vb0), tanhf(vb1), tanhf(vb2), tanhf(vb3));
                } else {
                    o0 = make_float4(sigm(va0), sigm(va1), sigm(va2), sigm(va3));
                    o1 = make_float4(sigm(vb0), sigm(vb1), sigm(vb2), sigm(vb3));
                }
                ST4(Gq + SWZ(jj, q0 + j), o0);
                ST4(Gq + SWZ(jj + 128, q0 + j), o1);
            }
        }
        __syncthreads();
#pragma unroll
        for (int i = 0; i < 8; i++) {
            int p = ft + 1024 * i;
            float4 iv = LD4(G0 + p), fv = LD4(G1 + p), gv = LD4(G2 + p), ov = LD4(G3 + p);
            float4 cv = LD4(Cs + p), cn, hv;
            cn.x = fv.x * cv.x + iv.x * gv.x;
            cn.y = fv.y * cv.y + iv.y * gv.y;
            cn.z = fv.z * cv.z + iv.z * gv.z;
            cn.w = fv.w * cv.w + iv.w * gv.w;
            hv.x = ov.x * tanhf(cn.x);
            hv.y = ov.y * tanhf(cn.y);
            hv.z = ov.z * tanhf(cn.z);
            hv.w = ov.w * tanhf(cn.w);
            ST4(Cs + p, cn);
            ST4(Hs + p, hv);
        }
        __syncthreads();
    }

    // ---- store h2 then c2 (coalesced across t) ----
    const size_t BH = (size_t)B_TOTAL * HDIM;
#pragma unroll 1
    for (int m = 0; m < MT; m++) {
        int sp = SWZ(t, m >> 2) + (m & 3);
        out[(size_t)(rowBase + m) * HDIM + t]      = Hs[sp];
        out[BH + (size_t)(rowBase + m) * HDIM + t] = Cs[sp];
    }
}

extern "C" void kernel_launch(void* const* d_in, const int* in_sizes, int n_in,
                              void* d_out, int out_size) {
    const float* x    = (const float*)d_in[0];
    const float* h0   = (const float*)d_in[1];
    const float* c0   = (const float*)d_in[2];
    const float* ts   = (const float*)d_in[3];
    const float* W_ih = (const float*)d_in[4];
    const float* W_hh = (const float*)d_in[5];
    const float* b_ih = (const float*)d_in[6];
    const float* b_hh = (const float*)d_in[7];
    const float* W1   = (const float*)d_in[8];
    const float* b1   = (const float*)d_in[9];
    const float* W2   = (const float*)d_in[10];
    const float* b2   = (const float*)d_in[11];
    float* out = (float*)d_out;

    cudaFuncSetAttribute(ode_lstm_kernel,
                         cudaFuncAttributeMaxDynamicSharedMemorySize, SMEM_BYTES);

    prep_kernel<<<512, 256>>>(W1, W2, W_ih, W_hh);
    ode_lstm_kernel<<<B_TOTAL / MT, TPB, SMEM_BYTES>>>(
        x, h0, c0, ts, b_ih, b_hh, b1, b2, out);
}